// round 4
// baseline (speedup 1.0000x reference)
#include <cuda_runtime.h>
#include <cuda_bf16.h>
#include <math.h>
#include <stdint.h>

#define NN 50000
#define NE 600000
#define NC 500
#define CE 8000
#define EPSV 1e-5f
#define SCAN_TILE 1024

// ---------------- scratch ----------------
__device__ float g_bufA[NN*128];
__device__ float g_bufB[NN*128];
__device__ float g_agg [NN*128];
__device__ float g_tmp [NN*128];
__device__ float g_cA  [NC*128];
__device__ float g_cB  [NC*128];
__device__ float g_cagg[NC*128];
__device__ float g_ctmp[NC*128];
__device__ float g_qkvN[(size_t)NN*384];
__device__ float g_qkvC[NC*384];
__device__ float g_hfinal[NN*128];
__device__ float g_z1  [NN*64];
__device__ int   g_degN [NN];
__device__ int   g_offN [NN+1];
__device__ int   g_fillN[NN];
__device__ int   g_colN [NE];
__device__ float g_wN   [NE];
__device__ float g_dinvN[NN];
__device__ int   g_degC [NC];
__device__ int   g_offC [NC+1];
__device__ int   g_fillC[NC];
__device__ int   g_colC [CE];
__device__ float g_wC   [CE];
__device__ float g_dinvC[NC];
__device__ float g_stats[7*256];
__device__ float g_WoT[128*128];
__device__ int   g_partials[128];
__device__ int   g_partoff [128];
// bf16 B-layout weights: node layers 0..2, comm 3..5 (16384 each), qkv at 6*16384
__device__ __nv_bfloat16 g_Bhi[6*16384 + 384*128];
__device__ __nv_bfloat16 g_Blo[6*16384 + 384*128];

// ---------------- helpers ----------------
__device__ __forceinline__ uint32_t smem_u32(const void* p) {
    uint32_t a;
    asm("{ .reg .u64 t; cvta.to.shared.u64 t, %1; cvt.u32.u64 %0, t; }" : "=r"(a) : "l"(p));
    return a;
}

#define LDSM_X4(r0,r1,r2,r3,addr) \
    asm volatile("ldmatrix.sync.aligned.m8n8.x4.shared.b16 {%0,%1,%2,%3}, [%4];" \
        : "=r"(r0),"=r"(r1),"=r"(r2),"=r"(r3) : "r"(addr))

#define MMA16816(d, a0,a1,a2,a3, b0,b1) \
    asm volatile("mma.sync.aligned.m16n8k16.row.col.f32.bf16.bf16.f32 " \
        "{%0,%1,%2,%3},{%4,%5,%6,%7},{%8,%9},{%0,%1,%2,%3};" \
        : "+f"((d)[0]),"+f"((d)[1]),"+f"((d)[2]),"+f"((d)[3]) \
        : "r"(a0),"r"(a1),"r"(a2),"r"(a3),"r"(b0),"r"(b1))

// padded bf16 tile: pitch = 136 elements (272 bytes)
#define TPITCH 272
#define TOFF(row, col) ((row)*TPITCH + (col)*2)
#define SA_HI 0
#define SA_LO 34816
#define SB_HI 69632
#define SB_LO 104448
#define SMEM_MMA 139264

// ---------------- mma GEMM: out[r][nOff+c] = sum_k A[r][k]*B[nOff+c][k] + bias ----------------
// grid (ceil(M/128), Ntot/128), 256 threads. A fp32 row-major [M x 128].
// Bhi/Blo bf16 [Ntot][128]. Split-bf16: D = AhBh + AhBl + AlBh.
__global__ __launch_bounds__(256) void mma_gemm_kernel(
        const float* __restrict__ A,
        const __nv_bfloat16* __restrict__ Bhi,
        const __nv_bfloat16* __restrict__ Blo,
        const float* __restrict__ bias,
        float* __restrict__ out, int ldOut, int M) {
    extern __shared__ char smem[];
    uint32_t sb = smem_u32(smem);
    const int t = threadIdx.x, lane = t & 31, wid = t >> 5;
    const int rowBase = blockIdx.x * 128;
    const int nOff = blockIdx.y * 128;

    // ---- load A: fp32 -> split bf16 into padded smem ----
    #pragma unroll 4
    for (int i = 0; i < 16; i++) {
        int flat = t + i * 256;              // float4 index
        int row = flat >> 5, col = (flat & 31) * 4;
        float4 v = make_float4(0.f, 0.f, 0.f, 0.f);
        if (rowBase + row < M) v = *(const float4*)(A + (size_t)(rowBase + row) * 128 + col);
        __nv_bfloat162 h01 = __floats2bfloat162_rn(v.x, v.y);
        __nv_bfloat162 h23 = __floats2bfloat162_rn(v.z, v.w);
        float rx = v.x - __bfloat162float(__low2bfloat16(h01));
        float ry = v.y - __bfloat162float(__high2bfloat16(h01));
        float rz = v.z - __bfloat162float(__low2bfloat16(h23));
        float rw = v.w - __bfloat162float(__high2bfloat16(h23));
        __nv_bfloat162 l01 = __floats2bfloat162_rn(rx, ry);
        __nv_bfloat162 l23 = __floats2bfloat162_rn(rz, rw);
        uint32_t o = TOFF(row, col);
        uint2 hw, lw;
        hw.x = *(uint32_t*)&h01; hw.y = *(uint32_t*)&h23;
        lw.x = *(uint32_t*)&l01; lw.y = *(uint32_t*)&l23;
        *(uint2*)(smem + SA_HI + o) = hw;
        *(uint2*)(smem + SA_LO + o) = lw;
    }
    // ---- load B tiles (already bf16) ----
    const uint4* bh = (const uint4*)(Bhi + (size_t)nOff * 128);
    const uint4* bl = (const uint4*)(Blo + (size_t)nOff * 128);
    #pragma unroll 4
    for (int i = 0; i < 8; i++) {
        int flat = t + i * 256;              // uint4 index: 16 per row
        int row = flat >> 4, col = (flat & 15) * 8;
        uint32_t o = TOFF(row, col);
        *(uint4*)(smem + SB_HI + o) = bh[flat];
        *(uint4*)(smem + SB_LO + o) = bl[flat];
    }
    __syncthreads();

    const int m0 = (wid & 3) * 32;           // warp M tile (2 x m16)
    const int n0 = (wid >> 2) * 64;          // warp N tile (8 x n8)

    // per-lane ldmatrix source coordinates
    const int aRow = m0 + (lane & 15);
    const int aColAdd = (lane >> 4) << 3;
    const int bRowRel = ((lane >> 4) << 3) + (lane & 7);
    const int bColAdd = ((lane >> 3) & 1) << 3;

    float d[2][8][4];
    #pragma unroll
    for (int mt = 0; mt < 2; mt++)
        #pragma unroll
        for (int nt = 0; nt < 8; nt++)
            #pragma unroll
            for (int j = 0; j < 4; j++) d[mt][nt][j] = 0.f;

    const int paOff[3] = {SA_HI, SA_HI, SA_LO};
    const int pbOff[3] = {SB_HI, SB_LO, SB_HI};

    #pragma unroll
    for (int p = 0; p < 3; p++) {
        uint32_t aBase = sb + paOff[p] + TOFF(aRow, aColAdd);
        uint32_t bBase = sb + pbOff[p] + TOFF(bRowRel, bColAdd);
        #pragma unroll
        for (int ks = 0; ks < 8; ks++) {
            int k0 = ks * 16;
            uint32_t a0[4], a1[4];
            LDSM_X4(a0[0],a0[1],a0[2],a0[3], aBase + k0*2);
            LDSM_X4(a1[0],a1[1],a1[2],a1[3], aBase + TOFF(16,0) + k0*2);
            #pragma unroll
            for (int np = 0; np < 4; np++) {
                uint32_t b0[2], b1[2];
                uint32_t bAddr = bBase + TOFF(n0 + np*16, 0) + k0*2;
                LDSM_X4(b0[0], b0[1], b1[0], b1[1], bAddr);
                MMA16816(d[0][np*2+0], a0[0],a0[1],a0[2],a0[3], b0[0],b0[1]);
                MMA16816(d[1][np*2+0], a1[0],a1[1],a1[2],a1[3], b0[0],b0[1]);
                MMA16816(d[0][np*2+1], a0[0],a0[1],a0[2],a0[3], b1[0],b1[1]);
                MMA16816(d[1][np*2+1], a1[0],a1[1],a1[2],a1[3], b1[0],b1[1]);
            }
        }
    }

    // ---- epilogue: d[mt][nt]: rows m0+mt*16+lane/4 (+8), cols n0+nt*8+(lane%3)*2 ----
    #pragma unroll
    for (int nt = 0; nt < 8; nt++) {
        int col = nOff + n0 + nt*8 + (lane & 3)*2;
        float b0v = bias[col], b1v = bias[col+1];
        #pragma unroll
        for (int mt = 0; mt < 2; mt++) {
            int r0 = rowBase + m0 + mt*16 + (lane >> 2);
            if (r0 < M) {
                float2 o0 = make_float2(d[mt][nt][0] + b0v, d[mt][nt][1] + b1v);
                *(float2*)(out + (size_t)r0 * ldOut + col) = o0;
            }
            int r1 = r0 + 8;
            if (r1 < M) {
                float2 o1 = make_float2(d[mt][nt][2] + b0v, d[mt][nt][3] + b1v);
                *(float2*)(out + (size_t)r1 * ldOut + col) = o1;
            }
        }
    }
}

// ---------------- weight conversion: fp32 -> split bf16, optional 128x128 transpose ----------------
__global__ void conv_w_kernel(const float* __restrict__ W, __nv_bfloat16* __restrict__ bhi,
                              __nv_bfloat16* __restrict__ blo, int total, int transpose) {
    int i = blockIdx.x * blockDim.x + threadIdx.x;
    if (i >= total) return;
    float v = W[i];
    __nv_bfloat16 h = __float2bfloat16(v);
    __nv_bfloat16 l = __float2bfloat16(v - __bfloat162float(h));
    int o = i;
    if (transpose) { int k = i >> 7, c = i & 127; o = c * 128 + k; }
    bhi[o] = h; blo[o] = l;
}

// ---------------- column stats reduce ----------------
__global__ void colstats_kernel(const float* __restrict__ x, float* __restrict__ stats, int n) {
    __shared__ float ssum[128], ssq[128];
    int t = threadIdx.x;           // 512 threads
    int c = t & 127, rl = t >> 7;
    float s = 0.f, q = 0.f;
    for (int r = blockIdx.x * 4 + rl; r < n; r += gridDim.x * 4) {
        float v = x[(size_t)r * 128 + c];
        s += v; q += v * v;
    }
    if (t < 128) { ssum[t] = 0.f; ssq[t] = 0.f; }
    __syncthreads();
    atomicAdd(&ssum[c], s); atomicAdd(&ssq[c], q);
    __syncthreads();
    if (t < 128) { atomicAdd(&stats[t], ssum[t]); atomicAdd(&stats[128 + t], ssq[t]); }
}

// ---------------- graph prep ----------------
__global__ void zero_kernel() {
    int i = blockIdx.x*blockDim.x + threadIdx.x;
    if (i < NN) { g_degN[i] = 0; g_fillN[i] = 0; }
    if (i < NC) { g_degC[i] = 0; g_fillC[i] = 0; }
    if (i < 7*256) g_stats[i] = 0.f;
}

__global__ void count_deg_kernel(const int* __restrict__ dst, int* __restrict__ deg, int ne) {
    int e = blockIdx.x*blockDim.x + threadIdx.x;
    if (e < ne) atomicAdd(&deg[dst[e]], 1);
}

__global__ void scan_partials_kernel(const int* __restrict__ cnt, int* __restrict__ partials, int n) {
    __shared__ int s[256];
    int t = threadIdx.x;
    int base = blockIdx.x * SCAN_TILE;
    int v = 0;
    #pragma unroll
    for (int j = 0; j < 4; j++) {
        int i = base + t + j*256;
        if (i < n) v += cnt[i];
    }
    s[t] = v; __syncthreads();
    for (int d = 128; d >= 1; d >>= 1) {
        if (t < d) s[t] += s[t+d];
        __syncthreads();
    }
    if (t == 0) partials[blockIdx.x] = s[0];
}

__global__ void scan_top_kernel(int* __restrict__ partials, int* __restrict__ partoff,
                                int* __restrict__ off, int n, int nb) {
    int t = threadIdx.x;
    __shared__ int s[128];
    int v = (t < nb) ? partials[t] : 0;
    s[t] = v; __syncthreads();
    int acc = 0;
    for (int i = 0; i < 128; i++) { if (i == t) break; acc += s[i]; }
    if (t < nb) partoff[t] = acc;
    if (t == 127) off[n] = acc + v;
}

__global__ void scan_final_kernel(const int* __restrict__ cnt, const int* __restrict__ partoff,
                                  int* __restrict__ off, int n) {
    __shared__ int s[256];
    int t = threadIdx.x;
    int base = blockIdx.x * SCAN_TILE;
    int v[4];
    int local = 0;
    #pragma unroll
    for (int j = 0; j < 4; j++) {
        int i = base + t*4 + j;
        v[j] = (i < n) ? cnt[i] : 0;
        local += v[j];
    }
    s[t] = local; __syncthreads();
    int x = local;
    #pragma unroll
    for (int d = 1; d < 256; d <<= 1) {
        int add = (t >= d) ? s[t-d] : 0;
        __syncthreads();
        s[t] += add;
        __syncthreads();
    }
    int tbase = partoff[blockIdx.x] + s[t] - x;
    #pragma unroll
    for (int j = 0; j < 4; j++) {
        int i = base + t*4 + j;
        if (i < n) { off[i] = tbase; tbase += v[j]; }
    }
}

__global__ void dinv_kernel(const int* __restrict__ deg, float* __restrict__ dinv, int n) {
    int i = blockIdx.x*blockDim.x + threadIdx.x;
    if (i < n) dinv[i] = 1.0f / sqrtf((float)(deg[i] + 1));
}

__global__ void fill_csr_kernel(const int* __restrict__ src, const int* __restrict__ dst,
                                const int* __restrict__ off, int* __restrict__ fill,
                                int* __restrict__ col, float* __restrict__ w,
                                const float* __restrict__ dinv, int ne) {
    int e = blockIdx.x*blockDim.x + threadIdx.x;
    if (e >= ne) return;
    int s = src[e], d = dst[e];
    int pos = off[d] + atomicAdd(&fill[d], 1);
    col[pos] = s;
    w[pos] = dinv[s] * dinv[d];
}

__global__ void transpose_wo_kernel(const float* __restrict__ wo) {
    int idx = blockIdx.x*blockDim.x + threadIdx.x;
    if (idx < 128*128) { int j = idx / 128, k = idx % 128; g_WoT[k*128 + j] = wo[idx]; }
}

// ---------------- GCN aggregation ----------------
__global__ void gcn_agg_kernel(const float* __restrict__ h, float* __restrict__ agg,
                               const int* __restrict__ off, const int* __restrict__ col,
                               const float* __restrict__ w, const float* __restrict__ dinv, int n) {
    int wid = (blockIdx.x*blockDim.x + threadIdx.x) >> 5;
    int lane = threadIdx.x & 31;
    if (wid >= n) return;
    float dv = dinv[wid];
    float sw = dv * dv;
    float4 hv = *(const float4*)(h + (size_t)wid*128 + lane*4);
    float4 acc = make_float4(sw*hv.x, sw*hv.y, sw*hv.z, sw*hv.w);
    int s = off[wid], e = off[wid+1];
    for (int j = s; j < e; j++) {
        int src = col[j];
        float ww = w[j];
        float4 xv = *(const float4*)(h + (size_t)src*128 + lane*4);
        acc.x += ww*xv.x; acc.y += ww*xv.y; acc.z += ww*xv.z; acc.w += ww*xv.w;
    }
    *(float4*)(agg + (size_t)wid*128 + lane*4) = acc;
}

// ---------------- BN + ReLU + optional residual ----------------
__global__ void bn_relu_res_kernel(const float* __restrict__ tin, const float* __restrict__ stats,
                                   const float* __restrict__ g, const float* __restrict__ b,
                                   const float* __restrict__ hprev, float* __restrict__ hout,
                                   int n, int residual) {
    int idx = blockIdx.x*blockDim.x + threadIdx.x;
    if (idx >= n*128) return;
    int c = idx & 127;
    float invN = 1.0f / (float)n;
    float mu = stats[c] * invN;
    float var = stats[128+c] * invN - mu*mu;
    float y = (tin[idx] - mu) / sqrtf(var + EPSV) * g[c] + b[c];
    y = fmaxf(y, 0.f);
    if (residual) y += hprev[idx];
    hout[idx] = y;
}

// ---------------- fused MHA + mean + residual + LayerNorm ----------------
__global__ void attn_fused_kernel(const float* __restrict__ qkvN, const float* __restrict__ qkvC,
                                  const int* __restrict__ map,
                                  const float* __restrict__ hnode,
                                  const float* __restrict__ WoT, const float* __restrict__ bo,
                                  const float* __restrict__ lng, const float* __restrict__ lnb,
                                  float* __restrict__ hfinal, int n) {
    extern __shared__ float sm[];
    float* sWoT = sm;
    float* sOm  = sm + 128*128;
    float4* sW4 = (float4*)sWoT;
    int t = threadIdx.x;
    #pragma unroll
    for (int j = 0; j < 16; j++) sW4[t + j*256] = ((const float4*)WoT)[t + j*256];
    __syncthreads();

    int lane = t & 31, warp = t >> 5;
    float4 bv  = ((const float4*)bo)[lane];
    float4 gv  = ((const float4*)lng)[lane];
    float4 bbv = ((const float4*)lnb)[lane];
    float* so = sOm + warp*128;

    for (int it = 0; it < 8; it++) {
        int node = blockIdx.x*64 + warp*8 + it;
        if (node >= n) break;
        int cm = map[node];
        cm = cm < 0 ? 0 : (cm > NC-1 ? NC-1 : cm);
        const float4* row0 = (const float4*)(qkvN + (size_t)node*384);
        const float4* row1 = (const float4*)(qkvC + (size_t)cm*384);
        float4 q0 = row0[lane],    q1 = row1[lane];
        float4 k0 = row0[32+lane], k1 = row1[32+lane];
        float4 v0 = row0[64+lane], v1 = row1[64+lane];

        float s00 = q0.x*k0.x + q0.y*k0.y + q0.z*k0.z + q0.w*k0.w;
        float s01 = q0.x*k1.x + q0.y*k1.y + q0.z*k1.z + q0.w*k1.w;
        float s10 = q1.x*k0.x + q1.y*k0.y + q1.z*k0.z + q1.w*k0.w;
        float s11 = q1.x*k1.x + q1.y*k1.y + q1.z*k1.z + q1.w*k1.w;
        #pragma unroll
        for (int m = 1; m <= 2; m <<= 1) {
            s00 += __shfl_xor_sync(0xffffffffu, s00, m);
            s01 += __shfl_xor_sync(0xffffffffu, s01, m);
            s10 += __shfl_xor_sync(0xffffffffu, s10, m);
            s11 += __shfl_xor_sync(0xffffffffu, s11, m);
        }
        s00 *= 0.25f; s01 *= 0.25f; s10 *= 0.25f; s11 *= 0.25f;
        float m0 = fmaxf(s00, s01);
        float e00 = expf(s00-m0), e01 = expf(s01-m0);
        float r0i = 1.f/(e00+e01);
        float p00 = e00*r0i, p01 = e01*r0i;
        float m1 = fmaxf(s10, s11);
        float e10 = expf(s10-m1), e11 = expf(s11-m1);
        float r1i = 1.f/(e10+e11);
        float p10 = e10*r1i, p11 = e11*r1i;

        float4 om;
        om.x = 0.5f*(p00*v0.x + p01*v1.x + p10*v0.x + p11*v1.x);
        om.y = 0.5f*(p00*v0.y + p01*v1.y + p10*v0.y + p11*v1.y);
        om.z = 0.5f*(p00*v0.z + p01*v1.z + p10*v0.z + p11*v1.z);
        om.w = 0.5f*(p00*v0.w + p01*v1.w + p10*v0.w + p11*v1.w);
        ((float4*)so)[lane] = om;
        __syncwarp();

        float4 acc = ((const float4*)(hnode + (size_t)node*128))[lane];
        acc.x += bv.x; acc.y += bv.y; acc.z += bv.z; acc.w += bv.w;
        #pragma unroll 8
        for (int k = 0; k < 128; k++) {
            float ok = so[k];
            float4 wv = sW4[k*32 + lane];
            acc.x = fmaf(ok, wv.x, acc.x);
            acc.y = fmaf(ok, wv.y, acc.y);
            acc.z = fmaf(ok, wv.z, acc.z);
            acc.w = fmaf(ok, wv.w, acc.w);
        }
        float sum = acc.x+acc.y+acc.z+acc.w;
        float sq  = acc.x*acc.x + acc.y*acc.y + acc.z*acc.z + acc.w*acc.w;
        #pragma unroll
        for (int m = 16; m >= 1; m >>= 1) {
            sum += __shfl_xor_sync(0xffffffffu, sum, m);
            sq  += __shfl_xor_sync(0xffffffffu, sq, m);
        }
        float mu = sum * (1.f/128.f);
        float var = sq * (1.f/128.f) - mu*mu;
        float inv = 1.f / sqrtf(var + EPSV);
        float4 o;
        o.x = (acc.x-mu)*inv*gv.x + bbv.x;
        o.y = (acc.y-mu)*inv*gv.y + bbv.y;
        o.z = (acc.z-mu)*inv*gv.z + bbv.z;
        o.w = (acc.w-mu)*inv*gv.w + bbv.w;
        ((float4*)(hfinal + (size_t)node*128))[lane] = o;
        __syncwarp();
    }
}

// ---------------- classifier GEMM1 (128->64) + stats ----------------
__global__ void cls_gemm1_kernel(const float* __restrict__ h, const float* __restrict__ W1,
                                 const float* __restrict__ b1, float* __restrict__ z,
                                 float* __restrict__ stats, int n) {
    __shared__ float sW[128*64];
    __shared__ float sRow[8][128];
    __shared__ float sSum[64], sSq[64];
    int t = threadIdx.x, lane = t & 31, warp = t >> 5;
    float4* sW4 = (float4*)sW;
    for (int j = t; j < 2048; j += 256) sW4[j] = ((const float4*)W1)[j];
    if (t < 64) { sSum[t] = 0.f; sSq[t] = 0.f; }
    __syncthreads();

    float2 ps = make_float2(0.f,0.f), psq = make_float2(0.f,0.f);
    float bx = b1[2*lane], by = b1[2*lane+1];
    for (int it = 0; it < 8; it++) {
        int row = blockIdx.x*64 + warp*8 + it;
        if (row < n) {
            ((float4*)sRow[warp])[lane] = ((const float4*)(h + (size_t)row*128))[lane];
            __syncwarp();
            float2 acc = make_float2(bx, by);
            #pragma unroll 8
            for (int k = 0; k < 128; k++) {
                float a = sRow[warp][k];
                float2 wv = ((float2*)sW)[k*32 + lane];
                acc.x = fmaf(a, wv.x, acc.x);
                acc.y = fmaf(a, wv.y, acc.y);
            }
            ((float2*)(z + (size_t)row*64))[lane] = acc;
            ps.x += acc.x; ps.y += acc.y;
            psq.x += acc.x*acc.x; psq.y += acc.y*acc.y;
            __syncwarp();
        }
    }
    atomicAdd(&sSum[2*lane],   ps.x); atomicAdd(&sSum[2*lane+1], ps.y);
    atomicAdd(&sSq [2*lane],   psq.x); atomicAdd(&sSq [2*lane+1], psq.y);
    __syncthreads();
    if (t < 64) { atomicAdd(&stats[t], sSum[t]); atomicAdd(&stats[64+t], sSq[t]); }
}

// ---------------- classifier tail ----------------
__global__ void cls_final_kernel(const float* __restrict__ z, const float* __restrict__ stats,
                                 const float* __restrict__ bng, const float* __restrict__ bnb,
                                 const float* __restrict__ W2, const float* __restrict__ b2,
                                 float* __restrict__ out, int n) {
    __shared__ float sW2[640];
    __shared__ float sb2[16];
    __shared__ float sZ[8][64];
    int t = threadIdx.x, lane = t & 31, warp = t >> 5;
    for (int j = t; j < 640; j += 256) sW2[j] = W2[j];
    if (t < 10) sb2[t] = b2[t];
    __syncthreads();

    float invN = 1.f / (float)n;
    int c0 = 2*lane, c1 = c0 + 1;
    float mu0 = stats[c0]*invN, mu1 = stats[c1]*invN;
    float v0 = stats[64+c0]*invN - mu0*mu0;
    float v1 = stats[64+c1]*invN - mu1*mu1;
    float sc0 = bng[c0] / sqrtf(v0 + EPSV);
    float sc1 = bng[c1] / sqrtf(v1 + EPSV);
    float sh0 = bnb[c0] - mu0*sc0;
    float sh1 = bnb[c1] - mu1*sc1;

    for (int it = 0; it < 8; it++) {
        int row = blockIdx.x*64 + warp*8 + it;
        if (row < n) {
            float2 zv = ((const float2*)(z + (size_t)row*64))[lane];
            sZ[warp][c0] = fmaxf(zv.x*sc0 + sh0, 0.f);
            sZ[warp][c1] = fmaxf(zv.y*sc1 + sh1, 0.f);
            __syncwarp();
            float logit = -1e30f;
            if (lane < 10) {
                logit = sb2[lane];
                #pragma unroll 8
                for (int k = 0; k < 64; k++) logit = fmaf(sZ[warp][k], sW2[k*10+lane], logit);
            }
            float mx = logit;
            #pragma unroll
            for (int m = 16; m >= 1; m >>= 1) mx = fmaxf(mx, __shfl_xor_sync(0xffffffffu, mx, m));
            float ex = (lane < 10) ? expf(logit - mx) : 0.f;
            float s = ex;
            #pragma unroll
            for (int m = 16; m >= 1; m >>= 1) s += __shfl_xor_sync(0xffffffffu, s, m);
            if (lane < 10) out[(size_t)row*10 + lane] = logit - mx - logf(s);
            __syncwarp();
        }
    }
}

// ---------------- host ----------------
extern "C" void kernel_launch(void* const* d_in, const int* in_sizes, int n_in,
                              void* d_out, int out_size) {
    const float* node_features = (const float*)d_in[0];
    const int*   node_ei       = (const int*)d_in[1];
    const float* comm_features = (const float*)d_in[2];
    const int*   comm_ei       = (const int*)d_in[3];
    const int*   n2c           = (const int*)d_in[4];
    const float* node_W   = (const float*)d_in[5];
    const float* node_b   = (const float*)d_in[6];
    const float* node_g   = (const float*)d_in[7];
    const float* node_be  = (const float*)d_in[8];
    const float* comm_W   = (const float*)d_in[9];
    const float* comm_b   = (const float*)d_in[10];
    const float* comm_g   = (const float*)d_in[11];
    const float* comm_be  = (const float*)d_in[12];
    const float* attn_in_w  = (const float*)d_in[13];
    const float* attn_in_b  = (const float*)d_in[14];
    const float* attn_out_w = (const float*)d_in[15];
    const float* attn_out_b = (const float*)d_in[16];
    const float* ln_g  = (const float*)d_in[17];
    const float* ln_b  = (const float*)d_in[18];
    const float* cls_W1 = (const float*)d_in[19];
    const float* cls_b1 = (const float*)d_in[20];
    const float* cls_bg = (const float*)d_in[21];
    const float* cls_bb = (const float*)d_in[22];
    const float* cls_W2 = (const float*)d_in[23];
    const float* cls_b2 = (const float*)d_in[24];
    float* out = (float*)d_out;

    float *bufA, *bufB, *agg, *tmp, *cA, *cB, *cagg, *ctmp, *qkvN, *qkvC, *hfinal, *z1;
    float *wN, *dinvN, *wC, *dinvC, *stats, *WoT;
    int *degN, *offN, *fillN, *colN, *degC, *offC, *fillC, *colC, *partials, *partoff;
    __nv_bfloat16 *Bhi, *Blo;
    cudaGetSymbolAddress((void**)&bufA, g_bufA);
    cudaGetSymbolAddress((void**)&bufB, g_bufB);
    cudaGetSymbolAddress((void**)&agg,  g_agg);
    cudaGetSymbolAddress((void**)&tmp,  g_tmp);
    cudaGetSymbolAddress((void**)&cA,   g_cA);
    cudaGetSymbolAddress((void**)&cB,   g_cB);
    cudaGetSymbolAddress((void**)&cagg, g_cagg);
    cudaGetSymbolAddress((void**)&ctmp, g_ctmp);
    cudaGetSymbolAddress((void**)&qkvN, g_qkvN);
    cudaGetSymbolAddress((void**)&qkvC, g_qkvC);
    cudaGetSymbolAddress((void**)&hfinal, g_hfinal);
    cudaGetSymbolAddress((void**)&z1,   g_z1);
    cudaGetSymbolAddress((void**)&degN, g_degN);
    cudaGetSymbolAddress((void**)&offN, g_offN);
    cudaGetSymbolAddress((void**)&fillN, g_fillN);
    cudaGetSymbolAddress((void**)&colN, g_colN);
    cudaGetSymbolAddress((void**)&wN,   g_wN);
    cudaGetSymbolAddress((void**)&dinvN, g_dinvN);
    cudaGetSymbolAddress((void**)&degC, g_degC);
    cudaGetSymbolAddress((void**)&offC, g_offC);
    cudaGetSymbolAddress((void**)&fillC, g_fillC);
    cudaGetSymbolAddress((void**)&colC, g_colC);
    cudaGetSymbolAddress((void**)&wC,   g_wC);
    cudaGetSymbolAddress((void**)&dinvC, g_dinvC);
    cudaGetSymbolAddress((void**)&stats, g_stats);
    cudaGetSymbolAddress((void**)&WoT,  g_WoT);
    cudaGetSymbolAddress((void**)&partials, g_partials);
    cudaGetSymbolAddress((void**)&partoff,  g_partoff);
    cudaGetSymbolAddress((void**)&Bhi,  g_Bhi);
    cudaGetSymbolAddress((void**)&Blo,  g_Blo);

    cudaFuncSetAttribute(mma_gemm_kernel,   cudaFuncAttributeMaxDynamicSharedMemorySize, SMEM_MMA);
    cudaFuncSetAttribute(attn_fused_kernel, cudaFuncAttributeMaxDynamicSharedMemorySize, 69632);

    // ---- graph prep + weight conversion ----
    zero_kernel<<<(NN+255)/256, 256>>>();
    count_deg_kernel<<<(NE+255)/256, 256>>>(node_ei + NE, degN, NE);
    count_deg_kernel<<<(CE+255)/256, 256>>>(comm_ei + CE, degC, CE);
    {
        int nb = (NN + SCAN_TILE - 1) / SCAN_TILE;
        scan_partials_kernel<<<nb, 256>>>(degN, partials, NN);
        scan_top_kernel<<<1, 128>>>(partials, partoff, offN, NN, nb);
        scan_final_kernel<<<nb, 256>>>(degN, partoff, offN, NN);
    }
    {
        int nb = (NC + SCAN_TILE - 1) / SCAN_TILE;
        scan_partials_kernel<<<nb, 256>>>(degC, partials, NC);
        scan_top_kernel<<<1, 128>>>(partials, partoff, offC, NC, nb);
        scan_final_kernel<<<nb, 256>>>(degC, partoff, offC, NC);
    }
    dinv_kernel<<<(NN+255)/256, 256>>>(degN, dinvN, NN);
    dinv_kernel<<<(NC+255)/256, 256>>>(degC, dinvC, NC);
    fill_csr_kernel<<<(NE+255)/256, 256>>>(node_ei, node_ei + NE, offN, fillN, colN, wN, dinvN, NE);
    fill_csr_kernel<<<(CE+255)/256, 256>>>(comm_ei, comm_ei + CE, offC, fillC, colC, wC, dinvC, CE);
    transpose_wo_kernel<<<(128*128+255)/256, 256>>>(attn_out_w);
    for (int i = 0; i < 3; i++) {
        conv_w_kernel<<<64, 256>>>(node_W + i*16384, Bhi + i*16384, Blo + i*16384, 16384, 1);
        conv_w_kernel<<<64, 256>>>(comm_W + i*16384, Bhi + (3+i)*16384, Blo + (3+i)*16384, 16384, 1);
    }
    conv_w_kernel<<<192, 256>>>(attn_in_w, Bhi + 6*16384, Blo + 6*16384, 384*128, 0);

    // ---- node GCN stack ----
    const float* hin = node_features;
    float* houts[3] = { bufA, bufB, bufA };
    int gN = (NN + 127) / 128;
    for (int i = 0; i < 3; i++) {
        gcn_agg_kernel<<<(NN*32+255)/256, 256>>>(hin, agg, offN, colN, wN, dinvN, NN);
        mma_gemm_kernel<<<dim3(gN, 1), 256, SMEM_MMA>>>(
            agg, Bhi + i*16384, Blo + i*16384, node_b + i*128, tmp, 128, NN);
        colstats_kernel<<<128, 512>>>(tmp, stats + i*256, NN);
        bn_relu_res_kernel<<<(NN*128+255)/256, 256>>>(
            tmp, stats + i*256, node_g + i*128, node_be + i*128, hin, houts[i], NN, i > 0);
        hin = houts[i];
    }
    const float* hnodeF = hin;

    // ---- comm GCN stack ----
    const float* cin = comm_features;
    float* couts[3] = { cA, cB, cA };
    int gC = (NC + 127) / 128;
    for (int i = 0; i < 3; i++) {
        gcn_agg_kernel<<<(NC*32+255)/256, 256>>>(cin, cagg, offC, colC, wC, dinvC, NC);
        mma_gemm_kernel<<<dim3(gC, 1), 256, SMEM_MMA>>>(
            cagg, Bhi + (3+i)*16384, Blo + (3+i)*16384, comm_b + i*128, ctmp, 128, NC);
        colstats_kernel<<<4, 512>>>(ctmp, stats + (3+i)*256, NC);
        bn_relu_res_kernel<<<(NC*128+255)/256, 256>>>(
            ctmp, stats + (3+i)*256, comm_g + i*128, comm_be + i*128, cin, couts[i], NC, i > 0);
        cin = couts[i];
    }
    const float* hcommF = cin;

    // ---- qkv GEMMs ----
    mma_gemm_kernel<<<dim3(gN, 3), 256, SMEM_MMA>>>(
        hnodeF, Bhi + 6*16384, Blo + 6*16384, attn_in_b, qkvN, 384, NN);
    mma_gemm_kernel<<<dim3(gC, 3), 256, SMEM_MMA>>>(
        hcommF, Bhi + 6*16384, Blo + 6*16384, attn_in_b, qkvC, 384, NC);

    // ---- fused attention + mean + residual + LayerNorm ----
    attn_fused_kernel<<<(NN+63)/64, 256, 69632>>>(
        qkvN, qkvC, n2c, hnodeF, WoT, attn_out_b, ln_g, ln_b, hfinal, NN);

    // ---- classifier ----
    cls_gemm1_kernel<<<(NN+63)/64, 256>>>(hfinal, cls_W1, cls_b1, z1, stats + 6*256, NN);
    cls_final_kernel<<<(NN+63)/64, 256>>>(z1, stats + 6*256, cls_bg, cls_bb, cls_W2, cls_b2, out, NN);
}

// round 5
// speedup vs baseline: 1.3561x; 1.3561x over previous
#include <cuda_runtime.h>
#include <math.h>
#include <stdint.h>

#define NN 50000
#define NE 600000
#define NC 500
#define CE 8000
#define EPSV 1e-5f
#define SCAN_TILE 1024

// ---------------- scratch ----------------
__device__ float g_bufA[NN*128];
__device__ float g_bufB[NN*128];
__device__ float g_agg [NN*128];
__device__ float g_tmp [NN*128];
__device__ float g_cA  [NC*128];
__device__ float g_cB  [NC*128];
__device__ float g_cagg[NC*128];
__device__ float g_ctmp[NC*128];
__device__ float g_qkvN[(size_t)NN*384];
__device__ float g_qkvC[NC*384];
__device__ float g_hfinal[NN*128];
__device__ float g_z1  [NN*64];
__device__ int   g_degN [NN];
__device__ int   g_offN [NN+1];
__device__ int   g_fillN[NN];
__device__ int   g_colN [NE];
__device__ float g_wN   [NE];
__device__ float g_dinvN[NN];
__device__ int   g_degC [NC];
__device__ int   g_offC [NC+1];
__device__ int   g_fillC[NC];
__device__ int   g_colC [CE];
__device__ float g_wC   [CE];
__device__ float g_dinvC[NC];
__device__ float g_stats[7*256];
__device__ float g_WiT[128*384];
__device__ float g_WoT[128*128];
__device__ int   g_partials[128];
__device__ int   g_partoff [128];

// ---------------- helpers ----------------
__device__ __forceinline__ uint32_t smem_u32(const void* p) {
    uint32_t a;
    asm("{ .reg .u64 t; cvta.to.shared.u64 t, %1; cvt.u32.u64 %0, t; }" : "=r"(a) : "l"(p));
    return a;
}
#define FMA2(acc, a, b) \
    asm("fma.rn.f32x2 %0, %1, %2, %0;" : "+l"(acc) : "l"(a), "l"(b))
#define DUP2(d, s) \
    asm("mov.b64 %0, {%1, %1};" : "=l"(d) : "f"(s))
#define PACK2(d, lo, hi) \
    asm("mov.b64 %0, {%1, %2};" : "=l"(d) : "f"(lo), "f"(hi))
#define LDS_V2B64(w0, w1, addr) \
    asm("ld.shared.v2.b64 {%0, %1}, [%2];" : "=l"(w0), "=l"(w1) : "r"(addr))
#define LDS_B64(w, addr) \
    asm("ld.shared.b64 %0, [%1];" : "=l"(w) : "r"(addr))

// ---------------- f32x2 GEMM: out[r][cOff+c] = sum_k A[r][k]*W[k][cOff+c] + bias ----------------
// grid (ceil(M/128), Ntot/128), 256 threads. Thread tile 8 rows x 8 cols
// (cols tc*4..+3 and 64+tc*4..+3). smem: sW[128][128] then sA[128][128] fp32.
template<bool STATS>
__global__ __launch_bounds__(256) void gemm_f32x2_kernel(
        const float* __restrict__ A,
        const float* __restrict__ W, int ldW,
        const float* __restrict__ bias,
        float* __restrict__ out, int ldOut,
        int M, float* __restrict__ stats) {
    extern __shared__ char smem[];
    float* sW = (float*)smem;
    float* sA = (float*)(smem + 65536);
    const int t = threadIdx.x;
    const int cOff = blockIdx.y * 128;
    const int rowBase = blockIdx.x * 128;

    // load W tile [128 k x 128 c]
    #pragma unroll 4
    for (int i = 0; i < 16; i++) {
        int flat = t + i*256;
        int k = flat >> 5, c4 = flat & 31;
        ((float4*)sW)[flat] = *(const float4*)(W + (size_t)k*ldW + cOff + c4*4);
    }
    // load A tile [128 r x 128 k]
    #pragma unroll 4
    for (int i = 0; i < 16; i++) {
        int flat = t + i*256;
        int r = flat >> 5, c4 = flat & 31;
        int gr = rowBase + r;
        float4 v = make_float4(0.f,0.f,0.f,0.f);
        if (gr < M) v = *(const float4*)(A + (size_t)gr*128 + c4*4);
        ((float4*)sA)[flat] = v;
    }
    __syncthreads();

    const int tc = t & 15, tr = t >> 4;
    const uint32_t sbase = smem_u32(smem);
    const uint32_t wA0 = sbase + tc*16;          // cols tc*4..+3
    const uint32_t wA1 = sbase + 256 + tc*16;    // cols 64+tc*4..+3

    unsigned long long acc[8][4];
    #pragma unroll
    for (int r = 0; r < 8; r++)
        #pragma unroll
        for (int j = 0; j < 4; j++) acc[r][j] = 0ull;

    #pragma unroll 2
    for (int k4 = 0; k4 < 32; k4++) {
        float4 a4[8];
        #pragma unroll
        for (int r = 0; r < 8; r++)
            a4[r] = *(const float4*)(sA + (tr*8 + r)*128 + k4*4);
        #pragma unroll
        for (int kk = 0; kk < 4; kk++) {
            uint32_t ka = (uint32_t)(k4*4 + kk) * 512;
            unsigned long long w0, w1, w2, w3;
            LDS_V2B64(w0, w1, wA0 + ka);
            LDS_V2B64(w2, w3, wA1 + ka);
            #pragma unroll
            for (int r = 0; r < 8; r++) {
                float av = ((const float*)&a4[r])[kk];
                unsigned long long ad;
                DUP2(ad, av);
                FMA2(acc[r][0], ad, w0);
                FMA2(acc[r][1], ad, w1);
                FMA2(acc[r][2], ad, w2);
                FMA2(acc[r][3], ad, w3);
            }
        }
    }

    float4 b0 = *(const float4*)(bias + cOff + tc*4);
    float4 b1 = *(const float4*)(bias + cOff + 64 + tc*4);
    float psum[8], psq[8];
    #pragma unroll
    for (int j = 0; j < 8; j++) { psum[j] = 0.f; psq[j] = 0.f; }

    #pragma unroll
    for (int r = 0; r < 8; r++) {
        int gr = rowBase + tr*8 + r;
        if (gr < M) {
            float2 p0 = *(float2*)&acc[r][0];
            float2 p1 = *(float2*)&acc[r][1];
            float2 p2 = *(float2*)&acc[r][2];
            float2 p3 = *(float2*)&acc[r][3];
            float4 o0 = make_float4(p0.x+b0.x, p0.y+b0.y, p1.x+b0.z, p1.y+b0.w);
            float4 o1 = make_float4(p2.x+b1.x, p2.y+b1.y, p3.x+b1.z, p3.y+b1.w);
            *(float4*)(out + (size_t)gr*ldOut + cOff + tc*4) = o0;
            *(float4*)(out + (size_t)gr*ldOut + cOff + 64 + tc*4) = o1;
            if (STATS) {
                psum[0]+=o0.x; psum[1]+=o0.y; psum[2]+=o0.z; psum[3]+=o0.w;
                psum[4]+=o1.x; psum[5]+=o1.y; psum[6]+=o1.z; psum[7]+=o1.w;
                psq[0]+=o0.x*o0.x; psq[1]+=o0.y*o0.y; psq[2]+=o0.z*o0.z; psq[3]+=o0.w*o0.w;
                psq[4]+=o1.x*o1.x; psq[5]+=o1.y*o1.y; psq[6]+=o1.z*o1.z; psq[7]+=o1.w*o1.w;
            }
        }
    }
    if (STATS) {
        __syncthreads();
        float* red = sA;   // 256 floats scratch
        red[t] = 0.f;
        __syncthreads();
        #pragma unroll
        for (int j = 0; j < 4; j++) {
            atomicAdd(&red[tc*4 + j], psum[j]);
            atomicAdd(&red[64 + tc*4 + j], psum[4+j]);
            atomicAdd(&red[128 + tc*4 + j], psq[j]);
            atomicAdd(&red[128 + 64 + tc*4 + j], psq[4+j]);
        }
        __syncthreads();
        if (t < 128) {
            atomicAdd(&stats[t], red[t]);
            atomicAdd(&stats[128 + t], red[128 + t]);
        }
    }
}

// ---------------- graph prep ----------------
__global__ void zero_kernel() {
    int i = blockIdx.x*blockDim.x + threadIdx.x;
    if (i < NN) { g_degN[i] = 0; g_fillN[i] = 0; }
    if (i < NC) { g_degC[i] = 0; g_fillC[i] = 0; }
    if (i < 7*256) g_stats[i] = 0.f;
}

__global__ void count_deg_kernel(const int* __restrict__ dst, int* __restrict__ deg, int ne) {
    int e = blockIdx.x*blockDim.x + threadIdx.x;
    if (e < ne) atomicAdd(&deg[dst[e]], 1);
}

__global__ void scan_partials_kernel(const int* __restrict__ cnt, int* __restrict__ partials, int n) {
    __shared__ int s[256];
    int t = threadIdx.x;
    int base = blockIdx.x * SCAN_TILE;
    int v = 0;
    #pragma unroll
    for (int j = 0; j < 4; j++) {
        int i = base + t + j*256;
        if (i < n) v += cnt[i];
    }
    s[t] = v; __syncthreads();
    for (int d = 128; d >= 1; d >>= 1) {
        if (t < d) s[t] += s[t+d];
        __syncthreads();
    }
    if (t == 0) partials[blockIdx.x] = s[0];
}

__global__ void scan_top_kernel(int* __restrict__ partials, int* __restrict__ partoff,
                                int* __restrict__ off, int n, int nb) {
    int t = threadIdx.x;
    __shared__ int s[128];
    int v = (t < nb) ? partials[t] : 0;
    s[t] = v; __syncthreads();
    int acc = 0;
    for (int i = 0; i < 128; i++) { if (i == t) break; acc += s[i]; }
    if (t < nb) partoff[t] = acc;
    if (t == 127) off[n] = acc + v;
}

__global__ void scan_final_kernel(const int* __restrict__ cnt, const int* __restrict__ partoff,
                                  int* __restrict__ off, int n) {
    __shared__ int s[256];
    int t = threadIdx.x;
    int base = blockIdx.x * SCAN_TILE;
    int v[4];
    int local = 0;
    #pragma unroll
    for (int j = 0; j < 4; j++) {
        int i = base + t*4 + j;
        v[j] = (i < n) ? cnt[i] : 0;
        local += v[j];
    }
    s[t] = local; __syncthreads();
    int x = local;
    #pragma unroll
    for (int d = 1; d < 256; d <<= 1) {
        int add = (t >= d) ? s[t-d] : 0;
        __syncthreads();
        s[t] += add;
        __syncthreads();
    }
    int tbase = partoff[blockIdx.x] + s[t] - x;
    #pragma unroll
    for (int j = 0; j < 4; j++) {
        int i = base + t*4 + j;
        if (i < n) { off[i] = tbase; tbase += v[j]; }
    }
}

__global__ void dinv_kernel(const int* __restrict__ deg, float* __restrict__ dinv, int n) {
    int i = blockIdx.x*blockDim.x + threadIdx.x;
    if (i < n) dinv[i] = 1.0f / sqrtf((float)(deg[i] + 1));
}

__global__ void fill_csr_kernel(const int* __restrict__ src, const int* __restrict__ dst,
                                const int* __restrict__ off, int* __restrict__ fill,
                                int* __restrict__ col, float* __restrict__ w,
                                const float* __restrict__ dinv, int ne) {
    int e = blockIdx.x*blockDim.x + threadIdx.x;
    if (e >= ne) return;
    int s = src[e], d = dst[e];
    int pos = off[d] + atomicAdd(&fill[d], 1);
    col[pos] = s;
    w[pos] = dinv[s] * dinv[d];
}

__global__ void transpose_w_kernel(const float* __restrict__ wi, const float* __restrict__ wo) {
    int idx = blockIdx.x*blockDim.x + threadIdx.x;
    if (idx < 384*128) { int j = idx / 128, k = idx % 128; g_WiT[k*384 + j] = wi[idx]; }
    if (idx < 128*128) { int j = idx / 128, k = idx % 128; g_WoT[k*128 + j] = wo[idx]; }
}

// ---------------- GCN aggregation ----------------
__global__ void gcn_agg_kernel(const float* __restrict__ h, float* __restrict__ agg,
                               const int* __restrict__ off, const int* __restrict__ col,
                               const float* __restrict__ w, const float* __restrict__ dinv, int n) {
    int wid = (blockIdx.x*blockDim.x + threadIdx.x) >> 5;
    int lane = threadIdx.x & 31;
    if (wid >= n) return;
    float dv = dinv[wid];
    float sw = dv * dv;
    float4 hv = *(const float4*)(h + (size_t)wid*128 + lane*4);
    float4 acc = make_float4(sw*hv.x, sw*hv.y, sw*hv.z, sw*hv.w);
    int s = off[wid], e = off[wid+1];
    for (int j = s; j < e; j++) {
        int src = col[j];
        float ww = w[j];
        float4 xv = *(const float4*)(h + (size_t)src*128 + lane*4);
        acc.x += ww*xv.x; acc.y += ww*xv.y; acc.z += ww*xv.z; acc.w += ww*xv.w;
    }
    *(float4*)(agg + (size_t)wid*128 + lane*4) = acc;
}

// ---------------- BN + ReLU + optional residual ----------------
__global__ void bn_relu_res_kernel(const float* __restrict__ tin, const float* __restrict__ stats,
                                   const float* __restrict__ g, const float* __restrict__ b,
                                   const float* __restrict__ hprev, float* __restrict__ hout,
                                   int n, int residual) {
    int idx = blockIdx.x*blockDim.x + threadIdx.x;
    if (idx >= n*128) return;
    int c = idx & 127;
    float invN = 1.0f / (float)n;
    float mu = stats[c] * invN;
    float var = stats[128+c] * invN - mu*mu;
    float y = (tin[idx] - mu) / sqrtf(var + EPSV) * g[c] + b[c];
    y = fmaxf(y, 0.f);
    if (residual) y += hprev[idx];
    hout[idx] = y;
}

// ---------------- fused MHA + mean + residual + LayerNorm ----------------
__global__ void attn_fused_kernel(const float* __restrict__ qkvN, const float* __restrict__ qkvC,
                                  const int* __restrict__ map,
                                  const float* __restrict__ hnode,
                                  const float* __restrict__ WoT, const float* __restrict__ bo,
                                  const float* __restrict__ lng, const float* __restrict__ lnb,
                                  float* __restrict__ hfinal, int n) {
    extern __shared__ float sm[];
    float* sWoT = sm;
    float* sOm  = sm + 128*128;
    float4* sW4 = (float4*)sWoT;
    int t = threadIdx.x;
    #pragma unroll
    for (int j = 0; j < 16; j++) sW4[t + j*256] = ((const float4*)WoT)[t + j*256];
    __syncthreads();

    int lane = t & 31, warp = t >> 5;
    uint32_t sWb = smem_u32(sm) + lane*16;
    float4 bv  = ((const float4*)bo)[lane];
    float4 gv  = ((const float4*)lng)[lane];
    float4 bbv = ((const float4*)lnb)[lane];
    float* so = sOm + warp*128;

    for (int it = 0; it < 8; it++) {
        int node = blockIdx.x*64 + warp*8 + it;
        if (node >= n) break;
        int cm = map[node];
        cm = cm < 0 ? 0 : (cm > NC-1 ? NC-1 : cm);
        const float4* row0 = (const float4*)(qkvN + (size_t)node*384);
        const float4* row1 = (const float4*)(qkvC + (size_t)cm*384);
        float4 q0 = row0[lane],    q1 = row1[lane];
        float4 k0 = row0[32+lane], k1 = row1[32+lane];
        float4 v0 = row0[64+lane], v1 = row1[64+lane];

        float s00 = q0.x*k0.x + q0.y*k0.y + q0.z*k0.z + q0.w*k0.w;
        float s01 = q0.x*k1.x + q0.y*k1.y + q0.z*k1.z + q0.w*k1.w;
        float s10 = q1.x*k0.x + q1.y*k0.y + q1.z*k0.z + q1.w*k0.w;
        float s11 = q1.x*k1.x + q1.y*k1.y + q1.z*k1.z + q1.w*k1.w;
        #pragma unroll
        for (int m = 1; m <= 2; m <<= 1) {
            s00 += __shfl_xor_sync(0xffffffffu, s00, m);
            s01 += __shfl_xor_sync(0xffffffffu, s01, m);
            s10 += __shfl_xor_sync(0xffffffffu, s10, m);
            s11 += __shfl_xor_sync(0xffffffffu, s11, m);
        }
        s00 *= 0.25f; s01 *= 0.25f; s10 *= 0.25f; s11 *= 0.25f;
        float m0 = fmaxf(s00, s01);
        float e00 = expf(s00-m0), e01 = expf(s01-m0);
        float r0i = 1.f/(e00+e01);
        float p00 = e00*r0i, p01 = e01*r0i;
        float m1 = fmaxf(s10, s11);
        float e10 = expf(s10-m1), e11 = expf(s11-m1);
        float r1i = 1.f/(e10+e11);
        float p10 = e10*r1i, p11 = e11*r1i;

        float4 om;
        om.x = 0.5f*(p00*v0.x + p01*v1.x + p10*v0.x + p11*v1.x);
        om.y = 0.5f*(p00*v0.y + p01*v1.y + p10*v0.y + p11*v1.y);
        om.z = 0.5f*(p00*v0.z + p01*v1.z + p10*v0.z + p11*v1.z);
        om.w = 0.5f*(p00*v0.w + p01*v1.w + p10*v0.w + p11*v1.w);
        ((float4*)so)[lane] = om;
        __syncwarp();

        float4 acc = ((const float4*)(hnode + (size_t)node*128))[lane];
        unsigned long long ap0, ap1;
        PACK2(ap0, acc.x + bv.x, acc.y + bv.y);
        PACK2(ap1, acc.z + bv.z, acc.w + bv.w);
        #pragma unroll 4
        for (int k4 = 0; k4 < 32; k4++) {
            float4 o4 = ((const float4*)so)[k4];
            #pragma unroll
            for (int kk = 0; kk < 4; kk++) {
                float ok = ((const float*)&o4)[kk];
                unsigned long long okd, w0, w1;
                DUP2(okd, ok);
                LDS_V2B64(w0, w1, sWb + (uint32_t)(k4*4 + kk)*512);
                FMA2(ap0, okd, w0);
                FMA2(ap1, okd, w1);
            }
        }
        float2 a01 = *(float2*)&ap0;
        float2 a23 = *(float2*)&ap1;
        acc.x = a01.x; acc.y = a01.y; acc.z = a23.x; acc.w = a23.y;

        float sum = acc.x+acc.y+acc.z+acc.w;
        float sq  = acc.x*acc.x + acc.y*acc.y + acc.z*acc.z + acc.w*acc.w;
        #pragma unroll
        for (int m = 16; m >= 1; m >>= 1) {
            sum += __shfl_xor_sync(0xffffffffu, sum, m);
            sq  += __shfl_xor_sync(0xffffffffu, sq, m);
        }
        float mu = sum * (1.f/128.f);
        float var = sq * (1.f/128.f) - mu*mu;
        float inv = 1.f / sqrtf(var + EPSV);
        float4 o;
        o.x = (acc.x-mu)*inv*gv.x + bbv.x;
        o.y = (acc.y-mu)*inv*gv.y + bbv.y;
        o.z = (acc.z-mu)*inv*gv.z + bbv.z;
        o.w = (acc.w-mu)*inv*gv.w + bbv.w;
        ((float4*)(hfinal + (size_t)node*128))[lane] = o;
        __syncwarp();
    }
}

// ---------------- classifier GEMM1 (128->64) + stats ----------------
__global__ void cls_gemm1_kernel(const float* __restrict__ h, const float* __restrict__ W1,
                                 const float* __restrict__ b1, float* __restrict__ z,
                                 float* __restrict__ stats, int n) {
    __shared__ float sW[128*64];
    __shared__ float sRow[8][128];
    __shared__ float sSum[64], sSq[64];
    int t = threadIdx.x, lane = t & 31, warp = t >> 5;
    float4* sW4 = (float4*)sW;
    for (int j = t; j < 2048; j += 256) sW4[j] = ((const float4*)W1)[j];
    if (t < 64) { sSum[t] = 0.f; sSq[t] = 0.f; }
    __syncthreads();

    uint32_t sWb = smem_u32(sW) + lane*8;
    float2 ps = make_float2(0.f,0.f), psq = make_float2(0.f,0.f);
    float bx = b1[2*lane], by = b1[2*lane+1];
    for (int it = 0; it < 8; it++) {
        int row = blockIdx.x*64 + warp*8 + it;
        if (row < n) {
            ((float4*)sRow[warp])[lane] = ((const float4*)(h + (size_t)row*128))[lane];
            __syncwarp();
            unsigned long long accp;
            PACK2(accp, bx, by);
            #pragma unroll 4
            for (int k4 = 0; k4 < 32; k4++) {
                float4 a4 = ((const float4*)sRow[warp])[k4];
                #pragma unroll
                for (int kk = 0; kk < 4; kk++) {
                    float a = ((const float*)&a4)[kk];
                    unsigned long long ad, w;
                    DUP2(ad, a);
                    LDS_B64(w, sWb + (uint32_t)(k4*4 + kk)*256);
                    FMA2(accp, ad, w);
                }
            }
            float2 acc = *(float2*)&accp;
            ((float2*)(z + (size_t)row*64))[lane] = acc;
            ps.x += acc.x; ps.y += acc.y;
            psq.x += acc.x*acc.x; psq.y += acc.y*acc.y;
            __syncwarp();
        }
    }
    atomicAdd(&sSum[2*lane],   ps.x); atomicAdd(&sSum[2*lane+1], ps.y);
    atomicAdd(&sSq [2*lane],   psq.x); atomicAdd(&sSq [2*lane+1], psq.y);
    __syncthreads();
    if (t < 64) { atomicAdd(&stats[t], sSum[t]); atomicAdd(&stats[64+t], sSq[t]); }
}

// ---------------- classifier tail ----------------
__global__ void cls_final_kernel(const float* __restrict__ z, const float* __restrict__ stats,
                                 const float* __restrict__ bng, const float* __restrict__ bnb,
                                 const float* __restrict__ W2, const float* __restrict__ b2,
                                 float* __restrict__ out, int n) {
    __shared__ float sW2[640];
    __shared__ float sb2[16];
    __shared__ float sZ[8][64];
    int t = threadIdx.x, lane = t & 31, warp = t >> 5;
    for (int j = t; j < 640; j += 256) sW2[j] = W2[j];
    if (t < 10) sb2[t] = b2[t];
    __syncthreads();

    float invN = 1.f / (float)n;
    int c0 = 2*lane, c1 = c0 + 1;
    float mu0 = stats[c0]*invN, mu1 = stats[c1]*invN;
    float v0 = stats[64+c0]*invN - mu0*mu0;
    float v1 = stats[64+c1]*invN - mu1*mu1;
    float sc0 = bng[c0] / sqrtf(v0 + EPSV);
    float sc1 = bng[c1] / sqrtf(v1 + EPSV);
    float sh0 = bnb[c0] - mu0*sc0;
    float sh1 = bnb[c1] - mu1*sc1;

    for (int it = 0; it < 8; it++) {
        int row = blockIdx.x*64 + warp*8 + it;
        if (row < n) {
            float2 zv = ((const float2*)(z + (size_t)row*64))[lane];
            sZ[warp][c0] = fmaxf(zv.x*sc0 + sh0, 0.f);
            sZ[warp][c1] = fmaxf(zv.y*sc1 + sh1, 0.f);
            __syncwarp();
            float logit = -1e30f;
            if (lane < 10) {
                logit = sb2[lane];
                #pragma unroll 8
                for (int k = 0; k < 64; k++) logit = fmaf(sZ[warp][k], sW2[k*10+lane], logit);
            }
            float mx = logit;
            #pragma unroll
            for (int m = 16; m >= 1; m >>= 1) mx = fmaxf(mx, __shfl_xor_sync(0xffffffffu, mx, m));
            float ex = (lane < 10) ? expf(logit - mx) : 0.f;
            float s = ex;
            #pragma unroll
            for (int m = 16; m >= 1; m >>= 1) s += __shfl_xor_sync(0xffffffffu, s, m);
            if (lane < 10) out[(size_t)row*10 + lane] = logit - mx - logf(s);
            __syncwarp();
        }
    }
}

// ---------------- host ----------------
extern "C" void kernel_launch(void* const* d_in, const int* in_sizes, int n_in,
                              void* d_out, int out_size) {
    const float* node_features = (const float*)d_in[0];
    const int*   node_ei       = (const int*)d_in[1];
    const float* comm_features = (const float*)d_in[2];
    const int*   comm_ei       = (const int*)d_in[3];
    const int*   n2c           = (const int*)d_in[4];
    const float* node_W   = (const float*)d_in[5];
    const float* node_b   = (const float*)d_in[6];
    const float* node_g   = (const float*)d_in[7];
    const float* node_be  = (const float*)d_in[8];
    const float* comm_W   = (const float*)d_in[9];
    const float* comm_b   = (const float*)d_in[10];
    const float* comm_g   = (const float*)d_in[11];
    const float* comm_be  = (const float*)d_in[12];
    const float* attn_in_w  = (const float*)d_in[13];
    const float* attn_in_b  = (const float*)d_in[14];
    const float* attn_out_w = (const float*)d_in[15];
    const float* attn_out_b = (const float*)d_in[16];
    const float* ln_g  = (const float*)d_in[17];
    const float* ln_b  = (const float*)d_in[18];
    const float* cls_W1 = (const float*)d_in[19];
    const float* cls_b1 = (const float*)d_in[20];
    const float* cls_bg = (const float*)d_in[21];
    const float* cls_bb = (const float*)d_in[22];
    const float* cls_W2 = (const float*)d_in[23];
    const float* cls_b2 = (const float*)d_in[24];
    float* out = (float*)d_out;

    float *bufA, *bufB, *agg, *tmp, *cA, *cB, *cagg, *ctmp, *qkvN, *qkvC, *hfinal, *z1;
    float *wN, *dinvN, *wC, *dinvC, *stats, *WiT, *WoT;
    int *degN, *offN, *fillN, *colN, *degC, *offC, *fillC, *colC, *partials, *partoff;
    cudaGetSymbolAddress((void**)&bufA, g_bufA);
    cudaGetSymbolAddress((void**)&bufB, g_bufB);
    cudaGetSymbolAddress((void**)&agg,  g_agg);
    cudaGetSymbolAddress((void**)&tmp,  g_tmp);
    cudaGetSymbolAddress((void**)&cA,   g_cA);
    cudaGetSymbolAddress((void**)&cB,   g_cB);
    cudaGetSymbolAddress((void**)&cagg, g_cagg);
    cudaGetSymbolAddress((void**)&ctmp, g_ctmp);
    cudaGetSymbolAddress((void**)&qkvN, g_qkvN);
    cudaGetSymbolAddress((void**)&qkvC, g_qkvC);
    cudaGetSymbolAddress((void**)&hfinal, g_hfinal);
    cudaGetSymbolAddress((void**)&z1,   g_z1);
    cudaGetSymbolAddress((void**)&degN, g_degN);
    cudaGetSymbolAddress((void**)&offN, g_offN);
    cudaGetSymbolAddress((void**)&fillN, g_fillN);
    cudaGetSymbolAddress((void**)&colN, g_colN);
    cudaGetSymbolAddress((void**)&wN,   g_wN);
    cudaGetSymbolAddress((void**)&dinvN, g_dinvN);
    cudaGetSymbolAddress((void**)&degC, g_degC);
    cudaGetSymbolAddress((void**)&offC, g_offC);
    cudaGetSymbolAddress((void**)&fillC, g_fillC);
    cudaGetSymbolAddress((void**)&colC, g_colC);
    cudaGetSymbolAddress((void**)&wC,   g_wC);
    cudaGetSymbolAddress((void**)&dinvC, g_dinvC);
    cudaGetSymbolAddress((void**)&stats, g_stats);
    cudaGetSymbolAddress((void**)&WiT,  g_WiT);
    cudaGetSymbolAddress((void**)&WoT,  g_WoT);
    cudaGetSymbolAddress((void**)&partials, g_partials);
    cudaGetSymbolAddress((void**)&partoff,  g_partoff);

    cudaFuncSetAttribute(gemm_f32x2_kernel<true>,  cudaFuncAttributeMaxDynamicSharedMemorySize, 131072);
    cudaFuncSetAttribute(gemm_f32x2_kernel<false>, cudaFuncAttributeMaxDynamicSharedMemorySize, 131072);
    cudaFuncSetAttribute(attn_fused_kernel,        cudaFuncAttributeMaxDynamicSharedMemorySize, 69632);

    // ---- graph prep ----
    zero_kernel<<<(NN+255)/256, 256>>>();
    count_deg_kernel<<<(NE+255)/256, 256>>>(node_ei + NE, degN, NE);
    count_deg_kernel<<<(CE+255)/256, 256>>>(comm_ei + CE, degC, CE);
    {
        int nb = (NN + SCAN_TILE - 1) / SCAN_TILE;
        scan_partials_kernel<<<nb, 256>>>(degN, partials, NN);
        scan_top_kernel<<<1, 128>>>(partials, partoff, offN, NN, nb);
        scan_final_kernel<<<nb, 256>>>(degN, partoff, offN, NN);
    }
    {
        int nb = (NC + SCAN_TILE - 1) / SCAN_TILE;
        scan_partials_kernel<<<nb, 256>>>(degC, partials, NC);
        scan_top_kernel<<<1, 128>>>(partials, partoff, offC, NC, nb);
        scan_final_kernel<<<nb, 256>>>(degC, partoff, offC, NC);
    }
    dinv_kernel<<<(NN+255)/256, 256>>>(degN, dinvN, NN);
    dinv_kernel<<<(NC+255)/256, 256>>>(degC, dinvC, NC);
    fill_csr_kernel<<<(NE+255)/256, 256>>>(node_ei, node_ei + NE, offN, fillN, colN, wN, dinvN, NE);
    fill_csr_kernel<<<(CE+255)/256, 256>>>(comm_ei, comm_ei + CE, offC, fillC, colC, wC, dinvC, CE);
    transpose_w_kernel<<<(384*128+255)/256, 256>>>(attn_in_w, attn_out_w);

    // ---- node GCN stack ----
    const float* hin = node_features;
    float* houts[3] = { bufA, bufB, bufA };
    int gN = (NN + 127) / 128;
    for (int i = 0; i < 3; i++) {
        gcn_agg_kernel<<<(NN*32+255)/256, 256>>>(hin, agg, offN, colN, wN, dinvN, NN);
        gemm_f32x2_kernel<true><<<dim3(gN, 1), 256, 131072>>>(
            agg, node_W + i*16384, 128, node_b + i*128, tmp, 128, NN, stats + i*256);
        bn_relu_res_kernel<<<(NN*128+255)/256, 256>>>(
            tmp, stats + i*256, node_g + i*128, node_be + i*128, hin, houts[i], NN, i > 0);
        hin = houts[i];
    }
    const float* hnodeF = hin;

    // ---- comm GCN stack ----
    const float* cin = comm_features;
    float* couts[3] = { cA, cB, cA };
    int gC = (NC + 127) / 128;
    for (int i = 0; i < 3; i++) {
        gcn_agg_kernel<<<(NC*32+255)/256, 256>>>(cin, cagg, offC, colC, wC, dinvC, NC);
        gemm_f32x2_kernel<true><<<dim3(gC, 1), 256, 131072>>>(
            cagg, comm_W + i*16384, 128, comm_b + i*128, ctmp, 128, NC, stats + (3+i)*256);
        bn_relu_res_kernel<<<(NC*128+255)/256, 256>>>(
            ctmp, stats + (3+i)*256, comm_g + i*128, comm_be + i*128, cin, couts[i], NC, i > 0);
        cin = couts[i];
    }
    const float* hcommF = cin;

    // ---- qkv GEMMs ----
    gemm_f32x2_kernel<false><<<dim3(gN, 3), 256, 131072>>>(
        hnodeF, WiT, 384, attn_in_b, qkvN, 384, NN, nullptr);
    gemm_f32x2_kernel<false><<<dim3(gC, 3), 256, 131072>>>(
        hcommF, WiT, 384, attn_in_b, qkvC, 384, NC, nullptr);

    // ---- fused attention + mean + residual + LayerNorm ----
    attn_fused_kernel<<<(NN+63)/64, 256, 69632>>>(
        qkvN, qkvC, n2c, hnodeF, WoT, attn_out_b, ln_g, ln_b, hfinal, NN);

    // ---- classifier ----
    cls_gemm1_kernel<<<(NN+63)/64, 256>>>(hfinal, cls_W1, cls_b1, z1, stats + 6*256, NN);
    cls_final_kernel<<<(NN+63)/64, 256>>>(z1, stats + 6*256, cls_bg, cls_bb, cls_W2, cls_b2, out, NN);
}

// round 6
// speedup vs baseline: 1.4296x; 1.0541x over previous
#include <cuda_runtime.h>
#include <math.h>
#include <stdint.h>

#define NN 50000
#define NE 600000
#define NC 500
#define CE 8000
#define EPSV 1e-5f
#define SCAN_TILE 1024

// ---------------- scratch ----------------
__device__ float g_bufA[NN*128];
__device__ float g_bufB[NN*128];
__device__ float g_agg [NN*128];
__device__ float g_tmp [NN*128];
__device__ float g_cA  [NC*128];
__device__ float g_cB  [NC*128];
__device__ float g_cagg[NC*128];
__device__ float g_ctmp[NC*128];
__device__ float g_qkvN[(size_t)NN*384];
__device__ float g_qkvC[NC*384];
__device__ float g_hfinal[NN*128];
__device__ float g_z1  [NN*64];
__device__ int   g_degN [NN];
__device__ int   g_offN [NN+1];
__device__ int   g_fillN[NN];
__device__ int   g_colN [NE];
__device__ float g_wN   [NE];
__device__ float g_dinvN[NN];
__device__ int   g_degC [NC];
__device__ int   g_offC [NC+1];
__device__ int   g_fillC[NC];
__device__ int   g_colC [CE];
__device__ float g_wC   [CE];
__device__ float g_dinvC[NC];
__device__ float g_stats[7*256];
__device__ float g_WiT[128*384];
__device__ float g_WoT[128*128];
__device__ int   g_partials[128];
__device__ int   g_partoff [128];

// ---------------- helpers ----------------
__device__ __forceinline__ uint32_t smem_u32(const void* p) {
    uint32_t a;
    asm("{ .reg .u64 t; cvta.to.shared.u64 t, %1; cvt.u32.u64 %0, t; }" : "=r"(a) : "l"(p));
    return a;
}
#define FMA2(acc, a, b) \
    asm("fma.rn.f32x2 %0, %1, %2, %0;" : "+l"(acc) : "l"(a), "l"(b))
#define DUP2(d, s) \
    asm("mov.b64 %0, {%1, %1};" : "=l"(d) : "f"(s))
#define PACK2(d, lo, hi) \
    asm("mov.b64 %0, {%1, %2};" : "=l"(d) : "f"(lo), "f"(hi))
#define UNPACK2(lo, hi, s) \
    asm("mov.b64 {%0, %1}, %2;" : "=f"(lo), "=f"(hi) : "l"(s))
#define LDS_V2B64(w0, w1, addr) \
    asm("ld.shared.v2.b64 {%0, %1}, [%2];" : "=l"(w0), "=l"(w1) : "r"(addr))
#define LDS_B64(w, addr) \
    asm("ld.shared.b64 %0, [%1];" : "=l"(w) : "r"(addr))

// ---------------- k-paired f32x2 GEMM ----------------
// out[r][cOff+c] = sum_k A[r][k]*W[k][cOff+c] + bias.
// grid (ceil(M/64), Ntot/128), 256 threads. Warp owns 8 rows; lane owns cols
// {lane, lane+32, lane+64, lane+96}. Accumulators hold {even-k, odd-k} partial
// pairs; horizontal add in epilogue. smem: sWp ull[64][128] (64KB) + sA float[64][128] (32KB).
template<bool STATS>
__global__ __launch_bounds__(256, 2) void gemm_kp_kernel(
        const float* __restrict__ A,
        const float* __restrict__ W, int ldW,
        const float* __restrict__ bias,
        float* __restrict__ out, int ldOut,
        int M, float* __restrict__ stats) {
    extern __shared__ char smem[];
    unsigned long long* sWp = (unsigned long long*)smem;
    float* sA = (float*)(smem + 65536);
    const int t = threadIdx.x;
    const int cOff = blockIdx.y * 128;
    const int rowBase = blockIdx.x * 64;

    // pack W k-pairs: sWp[kp][c] = {W[2kp][c], W[2kp+1][c]}
    #pragma unroll
    for (int i = 0; i < 8; i++) {
        int flat = t + i*256;                 // 2048 = 64 kp x 32 c4
        int kp = flat >> 5, c4 = (flat & 31) * 4;
        float4 w0 = *(const float4*)(W + (size_t)(2*kp)*ldW + cOff + c4);
        float4 w1 = *(const float4*)(W + (size_t)(2*kp+1)*ldW + cOff + c4);
        unsigned long long p0, p1, p2, p3;
        PACK2(p0, w0.x, w1.x); PACK2(p1, w0.y, w1.y);
        PACK2(p2, w0.z, w1.z); PACK2(p3, w0.w, w1.w);
        unsigned long long* dst = sWp + kp*128 + c4;
        dst[0] = p0; dst[1] = p1; dst[2] = p2; dst[3] = p3;
    }
    // load A tile [64 r][128 k]
    #pragma unroll
    for (int i = 0; i < 8; i++) {
        int flat = t + i*256;                 // 2048 float4
        int r = flat >> 5, c4 = flat & 31;
        int gr = rowBase + r;
        float4 v = make_float4(0.f,0.f,0.f,0.f);
        if (gr < M) v = *(const float4*)(A + (size_t)gr*128 + c4*4);
        ((float4*)sA)[flat] = v;
    }
    __syncthreads();

    const int lane = t & 31, warp = t >> 5;
    const int r0 = warp * 8;
    const uint32_t sbase = smem_u32(smem);
    const uint32_t wB = sbase + lane*8;             // ull col base (consecutive 8B per lane)
    const uint32_t aB = sbase + 65536 + r0*512;     // warp's A rows (bytes)

    unsigned long long acc[8][4];
    #pragma unroll
    for (int r = 0; r < 8; r++)
        #pragma unroll
        for (int j = 0; j < 4; j++) acc[r][j] = 0ull;

    #pragma unroll 4
    for (int kp = 0; kp < 64; kp++) {
        unsigned long long w0, w1, w2, w3;
        uint32_t wk = wB + (uint32_t)kp*1024;
        LDS_B64(w0, wk);
        LDS_B64(w1, wk + 256);
        LDS_B64(w2, wk + 512);
        LDS_B64(w3, wk + 768);
        #pragma unroll
        for (int r = 0; r < 8; r++) {
            unsigned long long a;                    // warp-uniform broadcast
            LDS_B64(a, aB + (uint32_t)r*512 + (uint32_t)kp*8);
            FMA2(acc[r][0], a, w0);
            FMA2(acc[r][1], a, w1);
            FMA2(acc[r][2], a, w2);
            FMA2(acc[r][3], a, w3);
        }
    }

    float bv[4];
    #pragma unroll
    for (int j = 0; j < 4; j++) bv[j] = bias[cOff + lane + j*32];
    float psum[4], psq[4];
    #pragma unroll
    for (int j = 0; j < 4; j++) { psum[j] = 0.f; psq[j] = 0.f; }

    #pragma unroll
    for (int r = 0; r < 8; r++) {
        int gr = rowBase + r0 + r;
        if (gr < M) {
            float* orow = out + (size_t)gr*ldOut + cOff + lane;
            #pragma unroll
            for (int j = 0; j < 4; j++) {
                float lo, hi;
                UNPACK2(lo, hi, acc[r][j]);
                float o = lo + hi + bv[j];
                orow[j*32] = o;
                if (STATS) { psum[j] += o; psq[j] += o*o; }
            }
        }
    }
    if (STATS) {
        __syncthreads();
        float* red = sA;                    // 256 floats scratch
        red[t] = 0.f;
        __syncthreads();
        #pragma unroll
        for (int j = 0; j < 4; j++) {
            atomicAdd(&red[lane + j*32], psum[j]);
            atomicAdd(&red[128 + lane + j*32], psq[j]);
        }
        __syncthreads();
        if (t < 128) {
            atomicAdd(&stats[t], red[t]);
            atomicAdd(&stats[128 + t], red[128 + t]);
        }
    }
}

// ---------------- graph prep ----------------
__global__ void zero_kernel() {
    int i = blockIdx.x*blockDim.x + threadIdx.x;
    if (i < NN) { g_degN[i] = 0; g_fillN[i] = 0; }
    if (i < NC) { g_degC[i] = 0; g_fillC[i] = 0; }
    if (i < 7*256) g_stats[i] = 0.f;
}

__global__ void count_deg_kernel(const int* __restrict__ dst, int* __restrict__ deg, int ne) {
    int e = blockIdx.x*blockDim.x + threadIdx.x;
    if (e < ne) atomicAdd(&deg[dst[e]], 1);
}

__global__ void scan_partials_kernel(const int* __restrict__ cnt, int* __restrict__ partials, int n) {
    __shared__ int s[256];
    int t = threadIdx.x;
    int base = blockIdx.x * SCAN_TILE;
    int v = 0;
    #pragma unroll
    for (int j = 0; j < 4; j++) {
        int i = base + t + j*256;
        if (i < n) v += cnt[i];
    }
    s[t] = v; __syncthreads();
    for (int d = 128; d >= 1; d >>= 1) {
        if (t < d) s[t] += s[t+d];
        __syncthreads();
    }
    if (t == 0) partials[blockIdx.x] = s[0];
}

__global__ void scan_top_kernel(int* __restrict__ partials, int* __restrict__ partoff,
                                int* __restrict__ off, int n, int nb) {
    int t = threadIdx.x;
    __shared__ int s[128];
    int v = (t < nb) ? partials[t] : 0;
    s[t] = v; __syncthreads();
    int acc = 0;
    for (int i = 0; i < 128; i++) { if (i == t) break; acc += s[i]; }
    if (t < nb) partoff[t] = acc;
    if (t == 127) off[n] = acc + v;
}

__global__ void scan_final_kernel(const int* __restrict__ cnt, const int* __restrict__ partoff,
                                  int* __restrict__ off, int n) {
    __shared__ int s[256];
    int t = threadIdx.x;
    int base = blockIdx.x * SCAN_TILE;
    int v[4];
    int local = 0;
    #pragma unroll
    for (int j = 0; j < 4; j++) {
        int i = base + t*4 + j;
        v[j] = (i < n) ? cnt[i] : 0;
        local += v[j];
    }
    s[t] = local; __syncthreads();
    int x = local;
    #pragma unroll
    for (int d = 1; d < 256; d <<= 1) {
        int add = (t >= d) ? s[t-d] : 0;
        __syncthreads();
        s[t] += add;
        __syncthreads();
    }
    int tbase = partoff[blockIdx.x] + s[t] - x;
    #pragma unroll
    for (int j = 0; j < 4; j++) {
        int i = base + t*4 + j;
        if (i < n) { off[i] = tbase; tbase += v[j]; }
    }
}

__global__ void dinv_kernel(const int* __restrict__ deg, float* __restrict__ dinv, int n) {
    int i = blockIdx.x*blockDim.x + threadIdx.x;
    if (i < n) dinv[i] = 1.0f / sqrtf((float)(deg[i] + 1));
}

__global__ void fill_csr_kernel(const int* __restrict__ src, const int* __restrict__ dst,
                                const int* __restrict__ off, int* __restrict__ fill,
                                int* __restrict__ col, float* __restrict__ w,
                                const float* __restrict__ dinv, int ne) {
    int e = blockIdx.x*blockDim.x + threadIdx.x;
    if (e >= ne) return;
    int s = src[e], d = dst[e];
    int pos = off[d] + atomicAdd(&fill[d], 1);
    col[pos] = s;
    w[pos] = dinv[s] * dinv[d];
}

__global__ void transpose_w_kernel(const float* __restrict__ wi, const float* __restrict__ wo) {
    int idx = blockIdx.x*blockDim.x + threadIdx.x;
    if (idx < 384*128) { int j = idx / 128, k = idx % 128; g_WiT[k*384 + j] = wi[idx]; }
    if (idx < 128*128) { int j = idx / 128, k = idx % 128; g_WoT[k*128 + j] = wo[idx]; }
}

// ---------------- GCN aggregation ----------------
__global__ void gcn_agg_kernel(const float* __restrict__ h, float* __restrict__ agg,
                               const int* __restrict__ off, const int* __restrict__ col,
                               const float* __restrict__ w, const float* __restrict__ dinv, int n) {
    int wid = (blockIdx.x*blockDim.x + threadIdx.x) >> 5;
    int lane = threadIdx.x & 31;
    if (wid >= n) return;
    float dv = dinv[wid];
    float sw = dv * dv;
    float4 hv = *(const float4*)(h + (size_t)wid*128 + lane*4);
    float4 acc = make_float4(sw*hv.x, sw*hv.y, sw*hv.z, sw*hv.w);
    int s = off[wid], e = off[wid+1];
    for (int j = s; j < e; j++) {
        int src = col[j];
        float ww = w[j];
        float4 xv = *(const float4*)(h + (size_t)src*128 + lane*4);
        acc.x += ww*xv.x; acc.y += ww*xv.y; acc.z += ww*xv.z; acc.w += ww*xv.w;
    }
    *(float4*)(agg + (size_t)wid*128 + lane*4) = acc;
}

// ---------------- BN + ReLU + optional residual ----------------
__global__ void bn_relu_res_kernel(const float* __restrict__ tin, const float* __restrict__ stats,
                                   const float* __restrict__ g, const float* __restrict__ b,
                                   const float* __restrict__ hprev, float* __restrict__ hout,
                                   int n, int residual) {
    int idx = blockIdx.x*blockDim.x + threadIdx.x;
    if (idx >= n*128) return;
    int c = idx & 127;
    float invN = 1.0f / (float)n;
    float mu = stats[c] * invN;
    float var = stats[128+c] * invN - mu*mu;
    float y = (tin[idx] - mu) / sqrtf(var + EPSV) * g[c] + b[c];
    y = fmaxf(y, 0.f);
    if (residual) y += hprev[idx];
    hout[idx] = y;
}

// ---------------- fused MHA + mean + residual + LayerNorm ----------------
__global__ void attn_fused_kernel(const float* __restrict__ qkvN, const float* __restrict__ qkvC,
                                  const int* __restrict__ map,
                                  const float* __restrict__ hnode,
                                  const float* __restrict__ WoT, const float* __restrict__ bo,
                                  const float* __restrict__ lng, const float* __restrict__ lnb,
                                  float* __restrict__ hfinal, int n) {
    extern __shared__ float sm[];
    float* sWoT = sm;
    float* sOm  = sm + 128*128;
    float4* sW4 = (float4*)sWoT;
    int t = threadIdx.x;
    #pragma unroll
    for (int j = 0; j < 16; j++) sW4[t + j*256] = ((const float4*)WoT)[t + j*256];
    __syncthreads();

    int lane = t & 31, warp = t >> 5;
    uint32_t sWb = smem_u32(sm) + lane*16;
    float4 bv  = ((const float4*)bo)[lane];
    float4 gv  = ((const float4*)lng)[lane];
    float4 bbv = ((const float4*)lnb)[lane];
    float* so = sOm + warp*128;

    for (int it = 0; it < 8; it++) {
        int node = blockIdx.x*64 + warp*8 + it;
        if (node >= n) break;
        int cm = map[node];
        cm = cm < 0 ? 0 : (cm > NC-1 ? NC-1 : cm);
        const float4* row0 = (const float4*)(qkvN + (size_t)node*384);
        const float4* row1 = (const float4*)(qkvC + (size_t)cm*384);
        float4 q0 = row0[lane],    q1 = row1[lane];
        float4 k0 = row0[32+lane], k1 = row1[32+lane];
        float4 v0 = row0[64+lane], v1 = row1[64+lane];

        float s00 = q0.x*k0.x + q0.y*k0.y + q0.z*k0.z + q0.w*k0.w;
        float s01 = q0.x*k1.x + q0.y*k1.y + q0.z*k1.z + q0.w*k1.w;
        float s10 = q1.x*k0.x + q1.y*k0.y + q1.z*k0.z + q1.w*k0.w;
        float s11 = q1.x*k1.x + q1.y*k1.y + q1.z*k1.z + q1.w*k1.w;
        #pragma unroll
        for (int m = 1; m <= 2; m <<= 1) {
            s00 += __shfl_xor_sync(0xffffffffu, s00, m);
            s01 += __shfl_xor_sync(0xffffffffu, s01, m);
            s10 += __shfl_xor_sync(0xffffffffu, s10, m);
            s11 += __shfl_xor_sync(0xffffffffu, s11, m);
        }
        s00 *= 0.25f; s01 *= 0.25f; s10 *= 0.25f; s11 *= 0.25f;
        float m0 = fmaxf(s00, s01);
        float e00 = expf(s00-m0), e01 = expf(s01-m0);
        float r0i = 1.f/(e00+e01);
        float p00 = e00*r0i, p01 = e01*r0i;
        float m1 = fmaxf(s10, s11);
        float e10 = expf(s10-m1), e11 = expf(s11-m1);
        float r1i = 1.f/(e10+e11);
        float p10 = e10*r1i, p11 = e11*r1i;

        float4 om;
        om.x = 0.5f*(p00*v0.x + p01*v1.x + p10*v0.x + p11*v1.x);
        om.y = 0.5f*(p00*v0.y + p01*v1.y + p10*v0.y + p11*v1.y);
        om.z = 0.5f*(p00*v0.z + p01*v1.z + p10*v0.z + p11*v1.z);
        om.w = 0.5f*(p00*v0.w + p01*v1.w + p10*v0.w + p11*v1.w);
        ((float4*)so)[lane] = om;
        __syncwarp();

        float4 acc = ((const float4*)(hnode + (size_t)node*128))[lane];
        unsigned long long ap0, ap1;
        PACK2(ap0, acc.x + bv.x, acc.y + bv.y);
        PACK2(ap1, acc.z + bv.z, acc.w + bv.w);
        #pragma unroll 4
        for (int k4 = 0; k4 < 32; k4++) {
            float4 o4 = ((const float4*)so)[k4];
            #pragma unroll
            for (int kk = 0; kk < 4; kk++) {
                float ok = ((const float*)&o4)[kk];
                unsigned long long okd, w0, w1;
                DUP2(okd, ok);
                LDS_V2B64(w0, w1, sWb + (uint32_t)(k4*4 + kk)*512);
                FMA2(ap0, okd, w0);
                FMA2(ap1, okd, w1);
            }
        }
        float2 a01, a23;
        UNPACK2(a01.x, a01.y, ap0);
        UNPACK2(a23.x, a23.y, ap1);
        acc.x = a01.x; acc.y = a01.y; acc.z = a23.x; acc.w = a23.y;

        float sum = acc.x+acc.y+acc.z+acc.w;
        float sq  = acc.x*acc.x + acc.y*acc.y + acc.z*acc.z + acc.w*acc.w;
        #pragma unroll
        for (int m = 16; m >= 1; m >>= 1) {
            sum += __shfl_xor_sync(0xffffffffu, sum, m);
            sq  += __shfl_xor_sync(0xffffffffu, sq, m);
        }
        float mu = sum * (1.f/128.f);
        float var = sq * (1.f/128.f) - mu*mu;
        float inv = 1.f / sqrtf(var + EPSV);
        float4 o;
        o.x = (acc.x-mu)*inv*gv.x + bbv.x;
        o.y = (acc.y-mu)*inv*gv.y + bbv.y;
        o.z = (acc.z-mu)*inv*gv.z + bbv.z;
        o.w = (acc.w-mu)*inv*gv.w + bbv.w;
        ((float4*)(hfinal + (size_t)node*128))[lane] = o;
        __syncwarp();
    }
}

// ---------------- classifier GEMM1 (128->64) + stats ----------------
__global__ void cls_gemm1_kernel(const float* __restrict__ h, const float* __restrict__ W1,
                                 const float* __restrict__ b1, float* __restrict__ z,
                                 float* __restrict__ stats, int n) {
    __shared__ float sW[128*64];
    __shared__ float sRow[8][128];
    __shared__ float sSum[64], sSq[64];
    int t = threadIdx.x, lane = t & 31, warp = t >> 5;
    float4* sW4 = (float4*)sW;
    for (int j = t; j < 2048; j += 256) sW4[j] = ((const float4*)W1)[j];
    if (t < 64) { sSum[t] = 0.f; sSq[t] = 0.f; }
    __syncthreads();

    uint32_t sWb = smem_u32(sW) + lane*8;
    float2 ps = make_float2(0.f,0.f), psq = make_float2(0.f,0.f);
    float bx = b1[2*lane], by = b1[2*lane+1];
    for (int it = 0; it < 8; it++) {
        int row = blockIdx.x*64 + warp*8 + it;
        if (row < n) {
            ((float4*)sRow[warp])[lane] = ((const float4*)(h + (size_t)row*128))[lane];
            __syncwarp();
            unsigned long long accp;
            PACK2(accp, bx, by);
            #pragma unroll 4
            for (int k4 = 0; k4 < 32; k4++) {
                float4 a4 = ((const float4*)sRow[warp])[k4];
                #pragma unroll
                for (int kk = 0; kk < 4; kk++) {
                    float a = ((const float*)&a4)[kk];
                    unsigned long long ad, w;
                    DUP2(ad, a);
                    LDS_B64(w, sWb + (uint32_t)(k4*4 + kk)*256);
                    FMA2(accp, ad, w);
                }
            }
            float2 acc;
            UNPACK2(acc.x, acc.y, accp);
            ((float2*)(z + (size_t)row*64))[lane] = acc;
            ps.x += acc.x; ps.y += acc.y;
            psq.x += acc.x*acc.x; psq.y += acc.y*acc.y;
            __syncwarp();
        }
    }
    atomicAdd(&sSum[2*lane],   ps.x); atomicAdd(&sSum[2*lane+1], ps.y);
    atomicAdd(&sSq [2*lane],   psq.x); atomicAdd(&sSq [2*lane+1], psq.y);
    __syncthreads();
    if (t < 64) { atomicAdd(&stats[t], sSum[t]); atomicAdd(&stats[64+t], sSq[t]); }
}

// ---------------- classifier tail ----------------
__global__ void cls_final_kernel(const float* __restrict__ z, const float* __restrict__ stats,
                                 const float* __restrict__ bng, const float* __restrict__ bnb,
                                 const float* __restrict__ W2, const float* __restrict__ b2,
                                 float* __restrict__ out, int n) {
    __shared__ float sW2[640];
    __shared__ float sb2[16];
    __shared__ float sZ[8][64];
    int t = threadIdx.x, lane = t & 31, warp = t >> 5;
    for (int j = t; j < 640; j += 256) sW2[j] = W2[j];
    if (t < 10) sb2[t] = b2[t];
    __syncthreads();

    float invN = 1.f / (float)n;
    int c0 = 2*lane, c1 = c0 + 1;
    float mu0 = stats[c0]*invN, mu1 = stats[c1]*invN;
    float v0 = stats[64+c0]*invN - mu0*mu0;
    float v1 = stats[64+c1]*invN - mu1*mu1;
    float sc0 = bng[c0] / sqrtf(v0 + EPSV);
    float sc1 = bng[c1] / sqrtf(v1 + EPSV);
    float sh0 = bnb[c0] - mu0*sc0;
    float sh1 = bnb[c1] - mu1*sc1;

    for (int it = 0; it < 8; it++) {
        int row = blockIdx.x*64 + warp*8 + it;
        if (row < n) {
            float2 zv = ((const float2*)(z + (size_t)row*64))[lane];
            sZ[warp][c0] = fmaxf(zv.x*sc0 + sh0, 0.f);
            sZ[warp][c1] = fmaxf(zv.y*sc1 + sh1, 0.f);
            __syncwarp();
            float logit = -1e30f;
            if (lane < 10) {
                logit = sb2[lane];
                #pragma unroll 8
                for (int k = 0; k < 64; k++) logit = fmaf(sZ[warp][k], sW2[k*10+lane], logit);
            }
            float mx = logit;
            #pragma unroll
            for (int m = 16; m >= 1; m >>= 1) mx = fmaxf(mx, __shfl_xor_sync(0xffffffffu, mx, m));
            float ex = (lane < 10) ? expf(logit - mx) : 0.f;
            float s = ex;
            #pragma unroll
            for (int m = 16; m >= 1; m >>= 1) s += __shfl_xor_sync(0xffffffffu, s, m);
            if (lane < 10) out[(size_t)row*10 + lane] = logit - mx - logf(s);
            __syncwarp();
        }
    }
}

// ---------------- host ----------------
extern "C" void kernel_launch(void* const* d_in, const int* in_sizes, int n_in,
                              void* d_out, int out_size) {
    const float* node_features = (const float*)d_in[0];
    const int*   node_ei       = (const int*)d_in[1];
    const float* comm_features = (const float*)d_in[2];
    const int*   comm_ei       = (const int*)d_in[3];
    const int*   n2c           = (const int*)d_in[4];
    const float* node_W   = (const float*)d_in[5];
    const float* node_b   = (const float*)d_in[6];
    const float* node_g   = (const float*)d_in[7];
    const float* node_be  = (const float*)d_in[8];
    const float* comm_W   = (const float*)d_in[9];
    const float* comm_b   = (const float*)d_in[10];
    const float* comm_g   = (const float*)d_in[11];
    const float* comm_be  = (const float*)d_in[12];
    const float* attn_in_w  = (const float*)d_in[13];
    const float* attn_in_b  = (const float*)d_in[14];
    const float* attn_out_w = (const float*)d_in[15];
    const float* attn_out_b = (const float*)d_in[16];
    const float* ln_g  = (const float*)d_in[17];
    const float* ln_b  = (const float*)d_in[18];
    const float* cls_W1 = (const float*)d_in[19];
    const float* cls_b1 = (const float*)d_in[20];
    const float* cls_bg = (const float*)d_in[21];
    const float* cls_bb = (const float*)d_in[22];
    const float* cls_W2 = (const float*)d_in[23];
    const float* cls_b2 = (const float*)d_in[24];
    float* out = (float*)d_out;

    float *bufA, *bufB, *agg, *tmp, *cA, *cB, *cagg, *ctmp, *qkvN, *qkvC, *hfinal, *z1;
    float *wN, *dinvN, *wC, *dinvC, *stats, *WiT, *WoT;
    int *degN, *offN, *fillN, *colN, *degC, *offC, *fillC, *colC, *partials, *partoff;
    cudaGetSymbolAddress((void**)&bufA, g_bufA);
    cudaGetSymbolAddress((void**)&bufB, g_bufB);
    cudaGetSymbolAddress((void**)&agg,  g_agg);
    cudaGetSymbolAddress((void**)&tmp,  g_tmp);
    cudaGetSymbolAddress((void**)&cA,   g_cA);
    cudaGetSymbolAddress((void**)&cB,   g_cB);
    cudaGetSymbolAddress((void**)&cagg, g_cagg);
    cudaGetSymbolAddress((void**)&ctmp, g_ctmp);
    cudaGetSymbolAddress((void**)&qkvN, g_qkvN);
    cudaGetSymbolAddress((void**)&qkvC, g_qkvC);
    cudaGetSymbolAddress((void**)&hfinal, g_hfinal);
    cudaGetSymbolAddress((void**)&z1,   g_z1);
    cudaGetSymbolAddress((void**)&degN, g_degN);
    cudaGetSymbolAddress((void**)&offN, g_offN);
    cudaGetSymbolAddress((void**)&fillN, g_fillN);
    cudaGetSymbolAddress((void**)&colN, g_colN);
    cudaGetSymbolAddress((void**)&wN,   g_wN);
    cudaGetSymbolAddress((void**)&dinvN, g_dinvN);
    cudaGetSymbolAddress((void**)&degC, g_degC);
    cudaGetSymbolAddress((void**)&offC, g_offC);
    cudaGetSymbolAddress((void**)&fillC, g_fillC);
    cudaGetSymbolAddress((void**)&colC, g_colC);
    cudaGetSymbolAddress((void**)&wC,   g_wC);
    cudaGetSymbolAddress((void**)&dinvC, g_dinvC);
    cudaGetSymbolAddress((void**)&stats, g_stats);
    cudaGetSymbolAddress((void**)&WiT,  g_WiT);
    cudaGetSymbolAddress((void**)&WoT,  g_WoT);
    cudaGetSymbolAddress((void**)&partials, g_partials);
    cudaGetSymbolAddress((void**)&partoff,  g_partoff);

    cudaFuncSetAttribute(gemm_kp_kernel<true>,  cudaFuncAttributeMaxDynamicSharedMemorySize, 98304);
    cudaFuncSetAttribute(gemm_kp_kernel<false>, cudaFuncAttributeMaxDynamicSharedMemorySize, 98304);
    cudaFuncSetAttribute(attn_fused_kernel,     cudaFuncAttributeMaxDynamicSharedMemorySize, 69632);

    // ---- graph prep ----
    zero_kernel<<<(NN+255)/256, 256>>>();
    count_deg_kernel<<<(NE+255)/256, 256>>>(node_ei + NE, degN, NE);
    count_deg_kernel<<<(CE+255)/256, 256>>>(comm_ei + CE, degC, CE);
    {
        int nb = (NN + SCAN_TILE - 1) / SCAN_TILE;
        scan_partials_kernel<<<nb, 256>>>(degN, partials, NN);
        scan_top_kernel<<<1, 128>>>(partials, partoff, offN, NN, nb);
        scan_final_kernel<<<nb, 256>>>(degN, partoff, offN, NN);
    }
    {
        int nb = (NC + SCAN_TILE - 1) / SCAN_TILE;
        scan_partials_kernel<<<nb, 256>>>(degC, partials, NC);
        scan_top_kernel<<<1, 128>>>(partials, partoff, offC, NC, nb);
        scan_final_kernel<<<nb, 256>>>(degC, partoff, offC, NC);
    }
    dinv_kernel<<<(NN+255)/256, 256>>>(degN, dinvN, NN);
    dinv_kernel<<<(NC+255)/256, 256>>>(degC, dinvC, NC);
    fill_csr_kernel<<<(NE+255)/256, 256>>>(node_ei, node_ei + NE, offN, fillN, colN, wN, dinvN, NE);
    fill_csr_kernel<<<(CE+255)/256, 256>>>(comm_ei, comm_ei + CE, offC, fillC, colC, wC, dinvC, CE);
    transpose_w_kernel<<<(384*128+255)/256, 256>>>(attn_in_w, attn_out_w);

    // ---- node GCN stack ----
    const float* hin = node_features;
    float* houts[3] = { bufA, bufB, bufA };
    int gN = (NN + 63) / 64;
    for (int i = 0; i < 3; i++) {
        gcn_agg_kernel<<<(NN*32+255)/256, 256>>>(hin, agg, offN, colN, wN, dinvN, NN);
        gemm_kp_kernel<true><<<dim3(gN, 1), 256, 98304>>>(
            agg, node_W + i*16384, 128, node_b + i*128, tmp, 128, NN, stats + i*256);
        bn_relu_res_kernel<<<(NN*128+255)/256, 256>>>(
            tmp, stats + i*256, node_g + i*128, node_be + i*128, hin, houts[i], NN, i > 0);
        hin = houts[i];
    }
    const float* hnodeF = hin;

    // ---- comm GCN stack ----
    const float* cin = comm_features;
    float* couts[3] = { cA, cB, cA };
    int gC = (NC + 63) / 64;
    for (int i = 0; i < 3; i++) {
        gcn_agg_kernel<<<(NC*32+255)/256, 256>>>(cin, cagg, offC, colC, wC, dinvC, NC);
        gemm_kp_kernel<true><<<dim3(gC, 1), 256, 98304>>>(
            cagg, comm_W + i*16384, 128, comm_b + i*128, ctmp, 128, NC, stats + (3+i)*256);
        bn_relu_res_kernel<<<(NC*128+255)/256, 256>>>(
            ctmp, stats + (3+i)*256, comm_g + i*128, comm_be + i*128, cin, couts[i], NC, i > 0);
        cin = couts[i];
    }
    const float* hcommF = cin;

    // ---- qkv GEMMs ----
    gemm_kp_kernel<false><<<dim3(gN, 3), 256, 98304>>>(
        hnodeF, WiT, 384, attn_in_b, qkvN, 384, NN, nullptr);
    gemm_kp_kernel<false><<<dim3(gC, 3), 256, 98304>>>(
        hcommF, WiT, 384, attn_in_b, qkvC, 384, NC, nullptr);

    // ---- fused attention + mean + residual + LayerNorm ----
    attn_fused_kernel<<<(NN+63)/64, 256, 69632>>>(
        qkvN, qkvC, n2c, hnodeF, WoT, attn_out_b, ln_g, ln_b, hfinal, NN);

    // ---- classifier ----
    cls_gemm1_kernel<<<(NN+63)/64, 256>>>(hfinal, cls_W1, cls_b1, z1, stats + 6*256, NN);
    cls_final_kernel<<<(NN+63)/64, 256>>>(z1, stats + 6*256, cls_bg, cls_bb, cls_W2, cls_b2, out, NN);
}

// round 7
// speedup vs baseline: 1.6126x; 1.1280x over previous
#include <cuda_runtime.h>
#include <math.h>
#include <stdint.h>

#define NN 50000
#define NE 600000
#define NC 500
#define CE 8000
#define EPSV 1e-5f
#define NBN 49        // (NN+1023)/1024
#define NBC 1
#define NBEN 2344     // (NE+255)/256
#define NBEC 32       // (CE+255)/256
#define GN 782        // (NN+63)/64
#define GC 8          // (NC+63)/64

// ---------------- scratch ----------------
__device__ float g_bufA[NN*128];
__device__ float g_bufB[NN*128];
__device__ float g_agg [NN*128];
__device__ float g_tmp [NN*128];
__device__ float g_cA  [NC*128];
__device__ float g_cB  [NC*128];
__device__ float g_cagg[NC*128];
__device__ float g_ctmp[NC*128];
__device__ float g_qkvN[(size_t)NN*384];
__device__ float g_qkvC[NC*384];
__device__ float g_hfinal[NN*128];
__device__ float g_z1  [NN*64];
__device__ int   g_degN [NN];
__device__ int   g_offN [NN+1];
__device__ int   g_fillN[NN];
__device__ int   g_colN [NE];
__device__ float g_wN   [NE];
__device__ float g_dinvN[NN];
__device__ int   g_degC [NC];
__device__ int   g_offC [NC+1];
__device__ int   g_fillC[NC];
__device__ int   g_colC [CE];
__device__ float g_wC   [CE];
__device__ float g_dinvC[NC];
__device__ float g_stats[7*256];
__device__ float g_WiT[128*384];
__device__ float g_WoT[128*128];
__device__ int   g_partials[128];   // [0..63] node, [64..] comm
__device__ int   g_partoff [128];

// ---------------- fused prep ----------------
__global__ void zero_kernel() {
    int i = blockIdx.x*blockDim.x + threadIdx.x;
    if (i < NN) { g_degN[i] = 0; g_fillN[i] = 0; }
    if (i < NC) { g_degC[i] = 0; g_fillC[i] = 0; }
    if (i < 7*256) g_stats[i] = 0.f;
}

__global__ void count_deg2_kernel(const int* __restrict__ ndst, const int* __restrict__ cdst) {
    int b = blockIdx.x;
    if (b < NBEN) {
        int e = b*256 + threadIdx.x;
        if (e < NE) atomicAdd(&g_degN[ndst[e]], 1);
    } else {
        int e = (b - NBEN)*256 + threadIdx.x;
        if (e < CE) atomicAdd(&g_degC[cdst[e]], 1);
    }
}

__global__ void scan_partials2_kernel() {
    __shared__ int s[256];
    int t = threadIdx.x;
    const int* cnt; int* partials; int n, bid;
    if (blockIdx.x < NBN) { cnt = g_degN; partials = g_partials; n = NN; bid = blockIdx.x; }
    else { cnt = g_degC; partials = g_partials + 64; n = NC; bid = blockIdx.x - NBN; }
    int base = bid * 1024;
    int v = 0;
    #pragma unroll
    for (int j = 0; j < 4; j++) {
        int i = base + t + j*256;
        if (i < n) v += cnt[i];
    }
    s[t] = v; __syncthreads();
    for (int d = 128; d >= 1; d >>= 1) {
        if (t < d) s[t] += s[t+d];
        __syncthreads();
    }
    if (t == 0) partials[bid] = s[0];
}

__global__ void scan_top2_kernel() {
    int t = threadIdx.x;   // 64 threads, 2 blocks
    __shared__ int s[64];
    const int* partials; int* partoff; int* off; int n, nb;
    if (blockIdx.x == 0) { partials = g_partials; partoff = g_partoff; off = g_offN; n = NN; nb = NBN; }
    else { partials = g_partials + 64; partoff = g_partoff + 64; off = g_offC; n = NC; nb = NBC; }
    int v = (t < nb) ? partials[t] : 0;
    s[t] = v; __syncthreads();
    int acc = 0;
    for (int i = 0; i < t; i++) acc += s[i];
    if (t < nb) partoff[t] = acc;
    if (t == 63) off[n] = acc + v;
}

__global__ void scan_final2_kernel() {
    __shared__ int s[256];
    int t = threadIdx.x;
    const int* cnt; const int* partoff; int* off; int n, bid;
    if (blockIdx.x < NBN) { cnt = g_degN; partoff = g_partoff; off = g_offN; n = NN; bid = blockIdx.x; }
    else { cnt = g_degC; partoff = g_partoff + 64; off = g_offC; n = NC; bid = blockIdx.x - NBN; }
    int base = bid * 1024;
    int v[4];
    int local = 0;
    #pragma unroll
    for (int j = 0; j < 4; j++) {
        int i = base + t*4 + j;
        v[j] = (i < n) ? cnt[i] : 0;
        local += v[j];
    }
    s[t] = local; __syncthreads();
    int x = local;
    #pragma unroll
    for (int d = 1; d < 256; d <<= 1) {
        int add = (t >= d) ? s[t-d] : 0;
        __syncthreads();
        s[t] += add;
        __syncthreads();
    }
    int tbase = partoff[bid] + s[t] - x;
    #pragma unroll
    for (int j = 0; j < 4; j++) {
        int i = base + t*4 + j;
        if (i < n) { off[i] = tbase; tbase += v[j]; }
    }
}

__global__ void dinv2_kernel() {
    int i = blockIdx.x*blockDim.x + threadIdx.x;
    if (i < NN) g_dinvN[i] = 1.0f / sqrtf((float)(g_degN[i] + 1));
    else if (i < NN + NC) {
        int c = i - NN;
        g_dinvC[c] = 1.0f / sqrtf((float)(g_degC[c] + 1));
    }
}

__global__ void fill_csr2_kernel(const int* __restrict__ nsrc, const int* __restrict__ ndst,
                                 const int* __restrict__ csrc, const int* __restrict__ cdst) {
    int b = blockIdx.x;
    if (b < NBEN) {
        int e = b*256 + threadIdx.x;
        if (e < NE) {
            int s = nsrc[e], d = ndst[e];
            int pos = g_offN[d] + atomicAdd(&g_fillN[d], 1);
            g_colN[pos] = s;
            g_wN[pos] = g_dinvN[s] * g_dinvN[d];
        }
    } else {
        int e = (b - NBEN)*256 + threadIdx.x;
        if (e < CE) {
            int s = csrc[e], d = cdst[e];
            int pos = g_offC[d] + atomicAdd(&g_fillC[d], 1);
            g_colC[pos] = s;
            g_wC[pos] = g_dinvC[s] * g_dinvC[d];
        }
    }
}

__global__ void transpose_w_kernel(const float* __restrict__ wi, const float* __restrict__ wo) {
    int idx = blockIdx.x*blockDim.x + threadIdx.x;
    if (idx < 384*128) { int j = idx / 128, k = idx % 128; g_WiT[k*384 + j] = wi[idx]; }
    if (idx < 128*128) { int j = idx / 128, k = idx % 128; g_WoT[k*128 + j] = wo[idx]; }
}

// ---------------- fused GCN aggregation (node + comm) ----------------
__global__ void gcn_agg2_kernel(const float* __restrict__ hN, float* __restrict__ aggN,
                                const float* __restrict__ hC, float* __restrict__ aggC) {
    int gw = (blockIdx.x*blockDim.x + threadIdx.x) >> 5;
    int lane = threadIdx.x & 31;
    const float* h; float* agg; const int* off; const int* col; const float* w; const float* dinv;
    int node;
    if (gw < NN) {
        h = hN; agg = aggN; off = g_offN; col = g_colN; w = g_wN; dinv = g_dinvN; node = gw;
    } else if (gw < NN + NC) {
        h = hC; agg = aggC; off = g_offC; col = g_colC; w = g_wC; dinv = g_dinvC; node = gw - NN;
    } else return;

    float dv = dinv[node];
    float sw = dv * dv;
    float4 hv = *(const float4*)(h + (size_t)node*128 + lane*4);
    float4 acc = make_float4(sw*hv.x, sw*hv.y, sw*hv.z, sw*hv.w);
    int s = off[node], e = off[node+1];
    int j = s;
    if (j < e) {
        int src = col[j]; float ww = w[j];
        for (; j + 1 < e; j++) {
            int nsrc = col[j+1]; float nww = w[j+1];   // prefetch indices
            float4 xv = *(const float4*)(h + (size_t)src*128 + lane*4);
            acc.x += ww*xv.x; acc.y += ww*xv.y; acc.z += ww*xv.z; acc.w += ww*xv.w;
            src = nsrc; ww = nww;
        }
        float4 xv = *(const float4*)(h + (size_t)src*128 + lane*4);
        acc.x += ww*xv.x; acc.y += ww*xv.y; acc.z += ww*xv.z; acc.w += ww*xv.w;
    }
    *(float4*)(agg + (size_t)node*128 + lane*4) = acc;
}

// ---------------- fused GEMM (node blocks + comm blocks), optional stats ----------------
// Body identical to the 723us R2 kernel: 64 rows x 128 cols per block, 256 threads,
// smem = sW 64KB + sA 32KB, warp owns 8 rows, thread 8x4 outputs.
template<bool STATS>
__global__ __launch_bounds__(256) void gemm2_kernel(
        const float* __restrict__ A0, const float* __restrict__ W0, const float* __restrict__ b0,
        float* __restrict__ out0, float* __restrict__ st0, int M0,
        const float* __restrict__ A1, const float* __restrict__ W1, const float* __restrict__ b1,
        float* __restrict__ out1, float* __restrict__ st1, int M1,
        int ldW, int ldOut) {
    extern __shared__ float sm[];
    float* sW = sm;               // 128*128
    float* sA = sm + 128*128;     // 64*128
    float4* sW4 = (float4*)sW;
    float4* sA4 = (float4*)sA;
    const int t = threadIdx.x;
    const int cOff = blockIdx.y * 128;

    const float *A, *W, *bias; float *out, *stats; int M, rowBase;
    if (blockIdx.x < GN) {
        A = A0; W = W0; bias = b0; out = out0; stats = st0; M = M0; rowBase = blockIdx.x * 64;
    } else {
        A = A1; W = W1; bias = b1; out = out1; stats = st1; M = M1; rowBase = (blockIdx.x - GN) * 64;
    }

    #pragma unroll
    for (int j = 0; j < 16; j++) {
        int g4 = t + j*256;
        int k = g4 >> 5, c4 = g4 & 31;
        sW4[g4] = *(const float4*)(W + (size_t)k*ldW + cOff + c4*4);
    }
    #pragma unroll
    for (int j = 0; j < 8; j++) {
        int g4 = t + j*256;
        int r = g4 >> 5, c4 = g4 & 31;
        int gr = rowBase + r;
        float4 v = make_float4(0.f, 0.f, 0.f, 0.f);
        if (gr < M) v = *(const float4*)(A + (size_t)gr*128 + c4*4);
        sA4[g4] = v;
    }
    __syncthreads();

    const int lane = t & 31, warp = t >> 5;
    const int r0 = warp * 8;
    float4 acc[8];
    #pragma unroll
    for (int r = 0; r < 8; r++) acc[r] = make_float4(0.f, 0.f, 0.f, 0.f);

    #pragma unroll 2
    for (int k4 = 0; k4 < 32; k4++) {
        float4 w0 = sW4[(k4*4+0)*32 + lane];
        float4 w1 = sW4[(k4*4+1)*32 + lane];
        float4 w2 = sW4[(k4*4+2)*32 + lane];
        float4 w3 = sW4[(k4*4+3)*32 + lane];
        #pragma unroll
        for (int r = 0; r < 8; r++) {
            float4 av = sA4[(r0+r)*32 + k4];
            acc[r].x = fmaf(av.x,w0.x, fmaf(av.y,w1.x, fmaf(av.z,w2.x, fmaf(av.w,w3.x, acc[r].x))));
            acc[r].y = fmaf(av.x,w0.y, fmaf(av.y,w1.y, fmaf(av.z,w2.y, fmaf(av.w,w3.y, acc[r].y))));
            acc[r].z = fmaf(av.x,w0.z, fmaf(av.y,w1.z, fmaf(av.z,w2.z, fmaf(av.w,w3.z, acc[r].z))));
            acc[r].w = fmaf(av.x,w0.w, fmaf(av.y,w1.w, fmaf(av.z,w2.w, fmaf(av.w,w3.w, acc[r].w))));
        }
    }

    float4 bv = *(const float4*)(bias + cOff + lane*4);
    float4 psum = make_float4(0.f,0.f,0.f,0.f), psq = make_float4(0.f,0.f,0.f,0.f);
    #pragma unroll
    for (int r = 0; r < 8; r++) {
        int gr = rowBase + r0 + r;
        if (gr < M) {
            float4 o = make_float4(acc[r].x+bv.x, acc[r].y+bv.y, acc[r].z+bv.z, acc[r].w+bv.w);
            *(float4*)(out + (size_t)gr*ldOut + cOff + lane*4) = o;
            if (STATS) {
                psum.x += o.x; psum.y += o.y; psum.z += o.z; psum.w += o.w;
                psq.x += o.x*o.x; psq.y += o.y*o.y; psq.z += o.z*o.z; psq.w += o.w*o.w;
            }
        }
    }
    if (STATS) {
        __syncthreads();
        float* sSum = sA;
        float* sSq  = sA + 128;
        if (t < 256) sA[t] = 0.f;
        __syncthreads();
        atomicAdd(&sSum[lane*4+0], psum.x); atomicAdd(&sSum[lane*4+1], psum.y);
        atomicAdd(&sSum[lane*4+2], psum.z); atomicAdd(&sSum[lane*4+3], psum.w);
        atomicAdd(&sSq [lane*4+0], psq.x);  atomicAdd(&sSq [lane*4+1], psq.y);
        atomicAdd(&sSq [lane*4+2], psq.z);  atomicAdd(&sSq [lane*4+3], psq.w);
        __syncthreads();
        if (t < 128) { atomicAdd(&stats[t], sSum[t]); atomicAdd(&stats[128+t], sSq[t]); }
    }
}

// ---------------- fused BN + ReLU + residual (node + comm), float4 ----------------
__global__ void bn2_kernel(const float* __restrict__ tN, const float* __restrict__ stN,
                           const float* __restrict__ gN, const float* __restrict__ bN,
                           const float* __restrict__ hpN, float* __restrict__ hoN,
                           const float* __restrict__ tC, const float* __restrict__ stC,
                           const float* __restrict__ gC, const float* __restrict__ bC,
                           const float* __restrict__ hpC, float* __restrict__ hoC,
                           int residual) {
    int idx = blockIdx.x*blockDim.x + threadIdx.x;   // float4 index
    const float *tin, *stats, *g, *b, *hp; float* ho; float invN;
    if (idx < NN*32) {
        tin = tN; stats = stN; g = gN; b = bN; hp = hpN; ho = hoN; invN = 1.0f/NN;
    } else if (idx < (NN+NC)*32) {
        idx -= NN*32;
        tin = tC; stats = stC; g = gC; b = bC; hp = hpC; ho = hoC; invN = 1.0f/NC;
    } else return;
    int c4 = (idx & 31) * 4;
    float4 mu4, v4, g4v, b4v;
    mu4 = *(const float4*)(stats + c4);
    v4  = *(const float4*)(stats + 128 + c4);
    g4v = *(const float4*)(g + c4);
    b4v = *(const float4*)(b + c4);
    float m0 = mu4.x*invN, m1 = mu4.y*invN, m2 = mu4.z*invN, m3 = mu4.w*invN;
    float s0 = g4v.x * rsqrtf(v4.x*invN - m0*m0 + EPSV);
    float s1 = g4v.y * rsqrtf(v4.y*invN - m1*m1 + EPSV);
    float s2 = g4v.z * rsqrtf(v4.z*invN - m2*m2 + EPSV);
    float s3 = g4v.w * rsqrtf(v4.w*invN - m3*m3 + EPSV);
    float4 x = ((const float4*)tin)[idx];
    float4 y;
    y.x = fmaxf((x.x - m0)*s0 + b4v.x, 0.f);
    y.y = fmaxf((x.y - m1)*s1 + b4v.y, 0.f);
    y.z = fmaxf((x.z - m2)*s2 + b4v.z, 0.f);
    y.w = fmaxf((x.w - m3)*s3 + b4v.w, 0.f);
    if (residual) {
        float4 p = ((const float4*)hp)[idx];
        y.x += p.x; y.y += p.y; y.z += p.z; y.w += p.w;
    }
    ((float4*)ho)[idx] = y;
}

// ---------------- fused MHA + mean + residual + LayerNorm (R2 version) ----------------
__global__ void attn_fused_kernel(const float* __restrict__ qkvN, const float* __restrict__ qkvC,
                                  const int* __restrict__ map,
                                  const float* __restrict__ hnode,
                                  const float* __restrict__ WoT, const float* __restrict__ bo,
                                  const float* __restrict__ lng, const float* __restrict__ lnb,
                                  float* __restrict__ hfinal, int n) {
    extern __shared__ float sm[];
    float* sWoT = sm;
    float* sOm  = sm + 128*128;
    float4* sW4 = (float4*)sWoT;
    int t = threadIdx.x;
    #pragma unroll
    for (int j = 0; j < 16; j++) sW4[t + j*256] = ((const float4*)WoT)[t + j*256];
    __syncthreads();

    int lane = t & 31, warp = t >> 5;
    float4 bv  = ((const float4*)bo)[lane];
    float4 gv  = ((const float4*)lng)[lane];
    float4 bbv = ((const float4*)lnb)[lane];
    float* so = sOm + warp*128;

    for (int it = 0; it < 8; it++) {
        int node = blockIdx.x*64 + warp*8 + it;
        if (node >= n) break;
        int cm = map[node];
        cm = cm < 0 ? 0 : (cm > NC-1 ? NC-1 : cm);
        const float4* row0 = (const float4*)(qkvN + (size_t)node*384);
        const float4* row1 = (const float4*)(qkvC + (size_t)cm*384);
        float4 q0 = row0[lane],    q1 = row1[lane];
        float4 k0 = row0[32+lane], k1 = row1[32+lane];
        float4 v0 = row0[64+lane], v1 = row1[64+lane];

        float s00 = q0.x*k0.x + q0.y*k0.y + q0.z*k0.z + q0.w*k0.w;
        float s01 = q0.x*k1.x + q0.y*k1.y + q0.z*k1.z + q0.w*k1.w;
        float s10 = q1.x*k0.x + q1.y*k0.y + q1.z*k0.z + q1.w*k0.w;
        float s11 = q1.x*k1.x + q1.y*k1.y + q1.z*k1.z + q1.w*k1.w;
        #pragma unroll
        for (int m = 1; m <= 2; m <<= 1) {
            s00 += __shfl_xor_sync(0xffffffffu, s00, m);
            s01 += __shfl_xor_sync(0xffffffffu, s01, m);
            s10 += __shfl_xor_sync(0xffffffffu, s10, m);
            s11 += __shfl_xor_sync(0xffffffffu, s11, m);
        }
        s00 *= 0.25f; s01 *= 0.25f; s10 *= 0.25f; s11 *= 0.25f;
        float m0 = fmaxf(s00, s01);
        float e00 = expf(s00-m0), e01 = expf(s01-m0);
        float r0i = 1.f/(e00+e01);
        float p00 = e00*r0i, p01 = e01*r0i;
        float m1 = fmaxf(s10, s11);
        float e10 = expf(s10-m1), e11 = expf(s11-m1);
        float r1i = 1.f/(e10+e11);
        float p10 = e10*r1i, p11 = e11*r1i;

        float4 om;
        om.x = 0.5f*(p00*v0.x + p01*v1.x + p10*v0.x + p11*v1.x);
        om.y = 0.5f*(p00*v0.y + p01*v1.y + p10*v0.y + p11*v1.y);
        om.z = 0.5f*(p00*v0.z + p01*v1.z + p10*v0.z + p11*v1.z);
        om.w = 0.5f*(p00*v0.w + p01*v1.w + p10*v0.w + p11*v1.w);
        ((float4*)so)[lane] = om;
        __syncwarp();

        float4 acc = ((const float4*)(hnode + (size_t)node*128))[lane];
        acc.x += bv.x; acc.y += bv.y; acc.z += bv.z; acc.w += bv.w;
        #pragma unroll 8
        for (int k = 0; k < 128; k++) {
            float ok = so[k];
            float4 wv = sW4[k*32 + lane];
            acc.x = fmaf(ok, wv.x, acc.x);
            acc.y = fmaf(ok, wv.y, acc.y);
            acc.z = fmaf(ok, wv.z, acc.z);
            acc.w = fmaf(ok, wv.w, acc.w);
        }
        float sum = acc.x+acc.y+acc.z+acc.w;
        float sq  = acc.x*acc.x + acc.y*acc.y + acc.z*acc.z + acc.w*acc.w;
        #pragma unroll
        for (int m = 16; m >= 1; m >>= 1) {
            sum += __shfl_xor_sync(0xffffffffu, sum, m);
            sq  += __shfl_xor_sync(0xffffffffu, sq, m);
        }
        float mu = sum * (1.f/128.f);
        float var = sq * (1.f/128.f) - mu*mu;
        float inv = 1.f / sqrtf(var + EPSV);
        float4 o;
        o.x = (acc.x-mu)*inv*gv.x + bbv.x;
        o.y = (acc.y-mu)*inv*gv.y + bbv.y;
        o.z = (acc.z-mu)*inv*gv.z + bbv.z;
        o.w = (acc.w-mu)*inv*gv.w + bbv.w;
        ((float4*)(hfinal + (size_t)node*128))[lane] = o;
        __syncwarp();
    }
}

// ---------------- classifier GEMM1 (128->64) + stats ----------------
__global__ void cls_gemm1_kernel(const float* __restrict__ h, const float* __restrict__ W1,
                                 const float* __restrict__ b1, float* __restrict__ z,
                                 float* __restrict__ stats, int n) {
    __shared__ float sW[128*64];
    __shared__ float sRow[8][128];
    __shared__ float sSum[64], sSq[64];
    int t = threadIdx.x, lane = t & 31, warp = t >> 5;
    float4* sW4 = (float4*)sW;
    for (int j = t; j < 2048; j += 256) sW4[j] = ((const float4*)W1)[j];
    if (t < 64) { sSum[t] = 0.f; sSq[t] = 0.f; }
    __syncthreads();

    float2 ps = make_float2(0.f,0.f), psq = make_float2(0.f,0.f);
    float bx = b1[2*lane], by = b1[2*lane+1];
    for (int it = 0; it < 8; it++) {
        int row = blockIdx.x*64 + warp*8 + it;
        if (row < n) {
            ((float4*)sRow[warp])[lane] = ((const float4*)(h + (size_t)row*128))[lane];
            __syncwarp();
            float2 acc = make_float2(bx, by);
            #pragma unroll 8
            for (int k = 0; k < 128; k++) {
                float a = sRow[warp][k];
                float2 wv = ((float2*)sW)[k*32 + lane];
                acc.x = fmaf(a, wv.x, acc.x);
                acc.y = fmaf(a, wv.y, acc.y);
            }
            ((float2*)(z + (size_t)row*64))[lane] = acc;
            ps.x += acc.x; ps.y += acc.y;
            psq.x += acc.x*acc.x; psq.y += acc.y*acc.y;
            __syncwarp();
        }
    }
    atomicAdd(&sSum[2*lane],   ps.x); atomicAdd(&sSum[2*lane+1], ps.y);
    atomicAdd(&sSq [2*lane],   psq.x); atomicAdd(&sSq [2*lane+1], psq.y);
    __syncthreads();
    if (t < 64) { atomicAdd(&stats[t], sSum[t]); atomicAdd(&stats[64+t], sSq[t]); }
}

// ---------------- classifier tail ----------------
__global__ void cls_final_kernel(const float* __restrict__ z, const float* __restrict__ stats,
                                 const float* __restrict__ bng, const float* __restrict__ bnb,
                                 const float* __restrict__ W2, const float* __restrict__ b2,
                                 float* __restrict__ out, int n) {
    __shared__ float sW2[640];
    __shared__ float sb2[16];
    __shared__ float sZ[8][64];
    int t = threadIdx.x, lane = t & 31, warp = t >> 5;
    for (int j = t; j < 640; j += 256) sW2[j] = W2[j];
    if (t < 10) sb2[t] = b2[t];
    __syncthreads();

    float invN = 1.f / (float)n;
    int c0 = 2*lane, c1 = c0 + 1;
    float mu0 = stats[c0]*invN, mu1 = stats[c1]*invN;
    float v0 = stats[64+c0]*invN - mu0*mu0;
    float v1 = stats[64+c1]*invN - mu1*mu1;
    float sc0 = bng[c0] / sqrtf(v0 + EPSV);
    float sc1 = bng[c1] / sqrtf(v1 + EPSV);
    float sh0 = bnb[c0] - mu0*sc0;
    float sh1 = bnb[c1] - mu1*sc1;

    for (int it = 0; it < 8; it++) {
        int row = blockIdx.x*64 + warp*8 + it;
        if (row < n) {
            float2 zv = ((const float2*)(z + (size_t)row*64))[lane];
            sZ[warp][c0] = fmaxf(zv.x*sc0 + sh0, 0.f);
            sZ[warp][c1] = fmaxf(zv.y*sc1 + sh1, 0.f);
            __syncwarp();
            float logit = -1e30f;
            if (lane < 10) {
                logit = sb2[lane];
                #pragma unroll 8
                for (int k = 0; k < 64; k++) logit = fmaf(sZ[warp][k], sW2[k*10+lane], logit);
            }
            float mx = logit;
            #pragma unroll
            for (int m = 16; m >= 1; m >>= 1) mx = fmaxf(mx, __shfl_xor_sync(0xffffffffu, mx, m));
            float ex = (lane < 10) ? expf(logit - mx) : 0.f;
            float s = ex;
            #pragma unroll
            for (int m = 16; m >= 1; m >>= 1) s += __shfl_xor_sync(0xffffffffu, s, m);
            if (lane < 10) out[(size_t)row*10 + lane] = logit - mx - logf(s);
            __syncwarp();
        }
    }
}

// ---------------- host ----------------
extern "C" void kernel_launch(void* const* d_in, const int* in_sizes, int n_in,
                              void* d_out, int out_size) {
    const float* node_features = (const float*)d_in[0];
    const int*   node_ei       = (const int*)d_in[1];
    const float* comm_features = (const float*)d_in[2];
    const int*   comm_ei       = (const int*)d_in[3];
    const int*   n2c           = (const int*)d_in[4];
    const float* node_W   = (const float*)d_in[5];
    const float* node_b   = (const float*)d_in[6];
    const float* node_g   = (const float*)d_in[7];
    const float* node_be  = (const float*)d_in[8];
    const float* comm_W   = (const float*)d_in[9];
    const float* comm_b   = (const float*)d_in[10];
    const float* comm_g   = (const float*)d_in[11];
    const float* comm_be  = (const float*)d_in[12];
    const float* attn_in_w  = (const float*)d_in[13];
    const float* attn_in_b  = (const float*)d_in[14];
    const float* attn_out_w = (const float*)d_in[15];
    const float* attn_out_b = (const float*)d_in[16];
    const float* ln_g  = (const float*)d_in[17];
    const float* ln_b  = (const float*)d_in[18];
    const float* cls_W1 = (const float*)d_in[19];
    const float* cls_b1 = (const float*)d_in[20];
    const float* cls_bg = (const float*)d_in[21];
    const float* cls_bb = (const float*)d_in[22];
    const float* cls_W2 = (const float*)d_in[23];
    const float* cls_b2 = (const float*)d_in[24];
    float* out = (float*)d_out;

    float *bufA, *bufB, *agg, *tmp, *cA, *cB, *cagg, *ctmp, *qkvN, *qkvC, *hfinal, *z1;
    float *stats, *WiT, *WoT;
    cudaGetSymbolAddress((void**)&bufA, g_bufA);
    cudaGetSymbolAddress((void**)&bufB, g_bufB);
    cudaGetSymbolAddress((void**)&agg,  g_agg);
    cudaGetSymbolAddress((void**)&tmp,  g_tmp);
    cudaGetSymbolAddress((void**)&cA,   g_cA);
    cudaGetSymbolAddress((void**)&cB,   g_cB);
    cudaGetSymbolAddress((void**)&cagg, g_cagg);
    cudaGetSymbolAddress((void**)&ctmp, g_ctmp);
    cudaGetSymbolAddress((void**)&qkvN, g_qkvN);
    cudaGetSymbolAddress((void**)&qkvC, g_qkvC);
    cudaGetSymbolAddress((void**)&hfinal, g_hfinal);
    cudaGetSymbolAddress((void**)&z1,   g_z1);
    cudaGetSymbolAddress((void**)&stats, g_stats);
    cudaGetSymbolAddress((void**)&WiT,  g_WiT);
    cudaGetSymbolAddress((void**)&WoT,  g_WoT);

    cudaFuncSetAttribute(gemm2_kernel<true>,  cudaFuncAttributeMaxDynamicSharedMemorySize, 98304);
    cudaFuncSetAttribute(gemm2_kernel<false>, cudaFuncAttributeMaxDynamicSharedMemorySize, 98304);
    cudaFuncSetAttribute(attn_fused_kernel,   cudaFuncAttributeMaxDynamicSharedMemorySize, 69632);

    // ---- fused graph prep ----
    zero_kernel<<<(NN+255)/256, 256>>>();
    count_deg2_kernel<<<NBEN + NBEC, 256>>>(node_ei + NE, comm_ei + CE);
    scan_partials2_kernel<<<NBN + NBC, 256>>>();
    scan_top2_kernel<<<2, 64>>>();
    scan_final2_kernel<<<NBN + NBC, 256>>>();
    dinv2_kernel<<<(NN + NC + 255)/256, 256>>>();
    fill_csr2_kernel<<<NBEN + NBEC, 256>>>(node_ei, node_ei + NE, comm_ei, comm_ei + CE);
    transpose_w_kernel<<<(384*128+255)/256, 256>>>(attn_in_w, attn_out_w);

    // ---- fused GCN stacks (node + comm in every launch) ----
    const float* hinN = node_features;
    const float* hinC = comm_features;
    float* houtsN[3] = { bufA, bufB, bufA };
    float* houtsC[3] = { cA, cB, cA };
    int aggWarps = NN + NC;
    for (int i = 0; i < 3; i++) {
        gcn_agg2_kernel<<<(aggWarps*32 + 255)/256, 256>>>(hinN, agg, hinC, cagg);
        gemm2_kernel<true><<<dim3(GN + GC, 1), 256, 98304>>>(
            agg,  node_W + i*16384, node_b + i*128, tmp,  stats + i*256,     NN,
            cagg, comm_W + i*16384, comm_b + i*128, ctmp, stats + (3+i)*256, NC,
            128, 128);
        bn2_kernel<<<((NN+NC)*32 + 255)/256, 256>>>(
            tmp,  stats + i*256,     node_g + i*128, node_be + i*128, hinN, houtsN[i],
            ctmp, stats + (3+i)*256, comm_g + i*128, comm_be + i*128, hinC, houtsC[i],
            i > 0);
        hinN = houtsN[i];
        hinC = houtsC[i];
    }

    // ---- fused qkv GEMM (node + comm) ----
    gemm2_kernel<false><<<dim3(GN + GC, 3), 256, 98304>>>(
        hinN, WiT, attn_in_b, qkvN, nullptr, NN,
        hinC, WiT, attn_in_b, qkvC, nullptr, NC,
        384, 384);

    // ---- fused attention + mean + residual + LayerNorm ----
    attn_fused_kernel<<<(NN+63)/64, 256, 69632>>>(
        qkvN, qkvC, n2c, hinN, WoT, attn_out_b, ln_g, ln_b, hfinal, NN);

    // ---- classifier ----
    cls_gemm1_kernel<<<(NN+63)/64, 256>>>(hfinal, cls_W1, cls_b1, z1, stats + 6*256, NN);
    cls_final_kernel<<<(NN+63)/64, 256>>>(z1, stats + 6*256, cls_bg, cls_bb, cls_W2, cls_b2, out, NN);
}

// round 8
// speedup vs baseline: 1.7023x; 1.0556x over previous
#include <cuda_runtime.h>
#include <math.h>
#include <stdint.h>

#define NN 50000
#define NE 600000
#define NC 500
#define CE 8000
#define EPSV 1e-5f
#define NBN 49        // (NN+1023)/1024
#define NBC 1
#define NBEN 2344     // (NE+255)/256
#define NBEC 32       // (CE+255)/256
#define GN 782        // (NN+63)/64
#define GC 8          // (NC+63)/64

// ---------------- scratch ----------------
__device__ float g_bufA[NN*128];
__device__ float g_bufB[NN*128];
__device__ float g_agg [NN*128];
__device__ float g_tmp [NN*128];
__device__ float g_cA  [NC*128];
__device__ float g_cB  [NC*128];
__device__ float g_cagg[NC*128];
__device__ float g_ctmp[NC*128];
__device__ float g_qkvN[(size_t)NN*384];
__device__ float g_qkvC[NC*384];
__device__ float g_z1  [NN*64];
__device__ int   g_degN [NN];
__device__ int   g_offN [NN+1];
__device__ int   g_fillN[NN];
__device__ int   g_colN [NE];
__device__ float g_wN   [NE];
__device__ float g_dinvN[NN];
__device__ int   g_degC [NC];
__device__ int   g_offC [NC+1];
__device__ int   g_fillC[NC];
__device__ int   g_colC [CE];
__device__ float g_wC   [CE];
__device__ float g_dinvC[NC];
__device__ float g_stats[7*256];
__device__ float g_WiT[128*384];
__device__ float g_WoT[128*128];
__device__ int   g_partials[128];   // [0..63] node, [64..] comm
__device__ int   g_partoff [128];

// ---------------- fused prep ----------------
__global__ void zero_kernel() {
    int i = blockIdx.x*blockDim.x + threadIdx.x;
    if (i < NN) { g_degN[i] = 0; g_fillN[i] = 0; }
    if (i < NC) { g_degC[i] = 0; g_fillC[i] = 0; }
    if (i < 7*256) g_stats[i] = 0.f;
}

__global__ void count_deg2_kernel(const int* __restrict__ ndst, const int* __restrict__ cdst) {
    int b = blockIdx.x;
    if (b < NBEN) {
        int e = b*256 + threadIdx.x;
        if (e < NE) atomicAdd(&g_degN[ndst[e]], 1);
    } else {
        int e = (b - NBEN)*256 + threadIdx.x;
        if (e < CE) atomicAdd(&g_degC[cdst[e]], 1);
    }
}

__global__ void scan_partials2_kernel() {
    __shared__ int s[256];
    int t = threadIdx.x;
    const int* cnt; int* partials; int n, bid;
    if (blockIdx.x < NBN) { cnt = g_degN; partials = g_partials; n = NN; bid = blockIdx.x; }
    else { cnt = g_degC; partials = g_partials + 64; n = NC; bid = blockIdx.x - NBN; }
    int base = bid * 1024;
    int v = 0;
    #pragma unroll
    for (int j = 0; j < 4; j++) {
        int i = base + t + j*256;
        if (i < n) v += cnt[i];
    }
    s[t] = v; __syncthreads();
    for (int d = 128; d >= 1; d >>= 1) {
        if (t < d) s[t] += s[t+d];
        __syncthreads();
    }
    if (t == 0) partials[bid] = s[0];
}

// parallel exclusive scan of <=64 partials via shfl
__global__ void scan_top2_kernel() {
    int t = threadIdx.x;   // 64 threads, 2 blocks
    const int* partials; int* partoff; int* off; int n, nb;
    if (blockIdx.x == 0) { partials = g_partials; partoff = g_partoff; off = g_offN; n = NN; nb = NBN; }
    else { partials = g_partials + 64; partoff = g_partoff + 64; off = g_offC; n = NC; nb = NBC; }
    int lane = t & 31, w = t >> 5;
    int v = (t < nb) ? partials[t] : 0;
    int inc = v;
    #pragma unroll
    for (int d = 1; d < 32; d <<= 1) {
        int tmp = __shfl_up_sync(0xffffffffu, inc, d);
        if (lane >= d) inc += tmp;
    }
    __shared__ int wsum[2];
    if (lane == 31) wsum[w] = inc;
    __syncthreads();
    int base = (w == 1) ? wsum[0] : 0;
    if (t < nb) partoff[t] = base + inc - v;
    if (t == 63) off[n] = base + inc;
}

// local scan + off write + dinv (fused)
__global__ void scan_final2_kernel() {
    __shared__ int s[256];
    int t = threadIdx.x;
    const int* cnt; const int* partoff; int* off; float* dinv; int n, bid;
    if (blockIdx.x < NBN) { cnt = g_degN; partoff = g_partoff; off = g_offN; dinv = g_dinvN; n = NN; bid = blockIdx.x; }
    else { cnt = g_degC; partoff = g_partoff + 64; off = g_offC; dinv = g_dinvC; n = NC; bid = blockIdx.x - NBN; }
    int base = bid * 1024;
    int v[4];
    int local = 0;
    #pragma unroll
    for (int j = 0; j < 4; j++) {
        int i = base + t*4 + j;
        v[j] = (i < n) ? cnt[i] : 0;
        local += v[j];
    }
    s[t] = local; __syncthreads();
    int x = local;
    #pragma unroll
    for (int d = 1; d < 256; d <<= 1) {
        int add = (t >= d) ? s[t-d] : 0;
        __syncthreads();
        s[t] += add;
        __syncthreads();
    }
    int tbase = partoff[bid] + s[t] - x;
    #pragma unroll
    for (int j = 0; j < 4; j++) {
        int i = base + t*4 + j;
        if (i < n) {
            off[i] = tbase; tbase += v[j];
            dinv[i] = 1.0f / sqrtf((float)(v[j] + 1));
        }
    }
}

__global__ void fill_csr2_kernel(const int* __restrict__ nsrc, const int* __restrict__ ndst,
                                 const int* __restrict__ csrc, const int* __restrict__ cdst) {
    int b = blockIdx.x;
    if (b < NBEN) {
        int e = b*256 + threadIdx.x;
        if (e < NE) {
            int s = nsrc[e], d = ndst[e];
            int pos = g_offN[d] + atomicAdd(&g_fillN[d], 1);
            g_colN[pos] = s;
            g_wN[pos] = g_dinvN[s] * g_dinvN[d];
        }
    } else {
        int e = (b - NBEN)*256 + threadIdx.x;
        if (e < CE) {
            int s = csrc[e], d = cdst[e];
            int pos = g_offC[d] + atomicAdd(&g_fillC[d], 1);
            g_colC[pos] = s;
            g_wC[pos] = g_dinvC[s] * g_dinvC[d];
        }
    }
}

__global__ void transpose_w_kernel(const float* __restrict__ wi, const float* __restrict__ wo) {
    int idx = blockIdx.x*blockDim.x + threadIdx.x;
    if (idx < 384*128) { int j = idx / 128, k = idx % 128; g_WiT[k*384 + j] = wi[idx]; }
    if (idx < 128*128) { int j = idx / 128, k = idx % 128; g_WoT[k*128 + j] = wo[idx]; }
}

// ---------------- fused GCN aggregation (node + comm) ----------------
__global__ void gcn_agg2_kernel(const float* __restrict__ hN, float* __restrict__ aggN,
                                const float* __restrict__ hC, float* __restrict__ aggC) {
    int gw = (blockIdx.x*blockDim.x + threadIdx.x) >> 5;
    int lane = threadIdx.x & 31;
    const float* h; float* agg; const int* off; const int* col; const float* w; const float* dinv;
    int node;
    if (gw < NN) {
        h = hN; agg = aggN; off = g_offN; col = g_colN; w = g_wN; dinv = g_dinvN; node = gw;
    } else if (gw < NN + NC) {
        h = hC; agg = aggC; off = g_offC; col = g_colC; w = g_wC; dinv = g_dinvC; node = gw - NN;
    } else return;

    float dv = dinv[node];
    float sw = dv * dv;
    float4 hv = *(const float4*)(h + (size_t)node*128 + lane*4);
    float4 acc = make_float4(sw*hv.x, sw*hv.y, sw*hv.z, sw*hv.w);
    int s = off[node], e = off[node+1];
    int j = s;
    if (j < e) {
        int src = col[j]; float ww = w[j];
        for (; j + 1 < e; j++) {
            int nsrc = col[j+1]; float nww = w[j+1];
            float4 xv = *(const float4*)(h + (size_t)src*128 + lane*4);
            acc.x += ww*xv.x; acc.y += ww*xv.y; acc.z += ww*xv.z; acc.w += ww*xv.w;
            src = nsrc; ww = nww;
        }
        float4 xv = *(const float4*)(h + (size_t)src*128 + lane*4);
        acc.x += ww*xv.x; acc.y += ww*xv.y; acc.z += ww*xv.z; acc.w += ww*xv.w;
    }
    *(float4*)(agg + (size_t)node*128 + lane*4) = acc;
}

// ---------------- fused GEMM (node blocks + comm blocks), optional stats ----------------
template<bool STATS>
__global__ __launch_bounds__(256) void gemm2_kernel(
        const float* __restrict__ A0, const float* __restrict__ W0, const float* __restrict__ b0,
        float* __restrict__ out0, float* __restrict__ st0, int M0,
        const float* __restrict__ A1, const float* __restrict__ W1, const float* __restrict__ b1,
        float* __restrict__ out1, float* __restrict__ st1, int M1,
        int ldW, int ldOut) {
    extern __shared__ float sm[];
    float* sW = sm;               // 128*128
    float* sA = sm + 128*128;     // 64*128
    float4* sW4 = (float4*)sW;
    float4* sA4 = (float4*)sA;
    const int t = threadIdx.x;
    const int cOff = blockIdx.y * 128;

    const float *A, *W, *bias; float *out, *stats; int M, rowBase;
    if (blockIdx.x < GN) {
        A = A0; W = W0; bias = b0; out = out0; stats = st0; M = M0; rowBase = blockIdx.x * 64;
    } else {
        A = A1; W = W1; bias = b1; out = out1; stats = st1; M = M1; rowBase = (blockIdx.x - GN) * 64;
    }

    #pragma unroll
    for (int j = 0; j < 16; j++) {
        int g4 = t + j*256;
        int k = g4 >> 5, c4 = g4 & 31;
        sW4[g4] = *(const float4*)(W + (size_t)k*ldW + cOff + c4*4);
    }
    #pragma unroll
    for (int j = 0; j < 8; j++) {
        int g4 = t + j*256;
        int r = g4 >> 5, c4 = g4 & 31;
        int gr = rowBase + r;
        float4 v = make_float4(0.f, 0.f, 0.f, 0.f);
        if (gr < M) v = *(const float4*)(A + (size_t)gr*128 + c4*4);
        sA4[g4] = v;
    }
    __syncthreads();

    const int lane = t & 31, warp = t >> 5;
    const int r0 = warp * 8;
    float4 acc[8];
    #pragma unroll
    for (int r = 0; r < 8; r++) acc[r] = make_float4(0.f, 0.f, 0.f, 0.f);

    #pragma unroll 2
    for (int k4 = 0; k4 < 32; k4++) {
        float4 w0 = sW4[(k4*4+0)*32 + lane];
        float4 w1 = sW4[(k4*4+1)*32 + lane];
        float4 w2 = sW4[(k4*4+2)*32 + lane];
        float4 w3 = sW4[(k4*4+3)*32 + lane];
        #pragma unroll
        for (int r = 0; r < 8; r++) {
            float4 av = sA4[(r0+r)*32 + k4];
            acc[r].x = fmaf(av.x,w0.x, fmaf(av.y,w1.x, fmaf(av.z,w2.x, fmaf(av.w,w3.x, acc[r].x))));
            acc[r].y = fmaf(av.x,w0.y, fmaf(av.y,w1.y, fmaf(av.z,w2.y, fmaf(av.w,w3.y, acc[r].y))));
            acc[r].z = fmaf(av.x,w0.z, fmaf(av.y,w1.z, fmaf(av.z,w2.z, fmaf(av.w,w3.z, acc[r].z))));
            acc[r].w = fmaf(av.x,w0.w, fmaf(av.y,w1.w, fmaf(av.z,w2.w, fmaf(av.w,w3.w, acc[r].w))));
        }
    }

    float4 bv = *(const float4*)(bias + cOff + lane*4);
    float4 psum = make_float4(0.f,0.f,0.f,0.f), psq = make_float4(0.f,0.f,0.f,0.f);
    #pragma unroll
    for (int r = 0; r < 8; r++) {
        int gr = rowBase + r0 + r;
        if (gr < M) {
            float4 o = make_float4(acc[r].x+bv.x, acc[r].y+bv.y, acc[r].z+bv.z, acc[r].w+bv.w);
            *(float4*)(out + (size_t)gr*ldOut + cOff + lane*4) = o;
            if (STATS) {
                psum.x += o.x; psum.y += o.y; psum.z += o.z; psum.w += o.w;
                psq.x += o.x*o.x; psq.y += o.y*o.y; psq.z += o.z*o.z; psq.w += o.w*o.w;
            }
        }
    }
    if (STATS) {
        __syncthreads();
        float* sSum = sA;
        float* sSq  = sA + 128;
        if (t < 256) sA[t] = 0.f;
        __syncthreads();
        atomicAdd(&sSum[lane*4+0], psum.x); atomicAdd(&sSum[lane*4+1], psum.y);
        atomicAdd(&sSum[lane*4+2], psum.z); atomicAdd(&sSum[lane*4+3], psum.w);
        atomicAdd(&sSq [lane*4+0], psq.x);  atomicAdd(&sSq [lane*4+1], psq.y);
        atomicAdd(&sSq [lane*4+2], psq.z);  atomicAdd(&sSq [lane*4+3], psq.w);
        __syncthreads();
        if (t < 128) { atomicAdd(&stats[t], sSum[t]); atomicAdd(&stats[128+t], sSq[t]); }
    }
}

// ---------------- fused BN + ReLU + residual (node + comm), float4 ----------------
__global__ void bn2_kernel(const float* __restrict__ tN, const float* __restrict__ stN,
                           const float* __restrict__ gN, const float* __restrict__ bN,
                           const float* __restrict__ hpN, float* __restrict__ hoN,
                           const float* __restrict__ tC, const float* __restrict__ stC,
                           const float* __restrict__ gC, const float* __restrict__ bC,
                           const float* __restrict__ hpC, float* __restrict__ hoC,
                           int residual) {
    int idx = blockIdx.x*blockDim.x + threadIdx.x;
    const float *tin, *stats, *g, *b, *hp; float* ho; float invN;
    if (idx < NN*32) {
        tin = tN; stats = stN; g = gN; b = bN; hp = hpN; ho = hoN; invN = 1.0f/NN;
    } else if (idx < (NN+NC)*32) {
        idx -= NN*32;
        tin = tC; stats = stC; g = gC; b = bC; hp = hpC; ho = hoC; invN = 1.0f/NC;
    } else return;
    int c4 = (idx & 31) * 4;
    float4 mu4 = *(const float4*)(stats + c4);
    float4 v4  = *(const float4*)(stats + 128 + c4);
    float4 g4v = *(const float4*)(g + c4);
    float4 b4v = *(const float4*)(b + c4);
    float m0 = mu4.x*invN, m1 = mu4.y*invN, m2 = mu4.z*invN, m3 = mu4.w*invN;
    float s0 = g4v.x * rsqrtf(v4.x*invN - m0*m0 + EPSV);
    float s1 = g4v.y * rsqrtf(v4.y*invN - m1*m1 + EPSV);
    float s2 = g4v.z * rsqrtf(v4.z*invN - m2*m2 + EPSV);
    float s3 = g4v.w * rsqrtf(v4.w*invN - m3*m3 + EPSV);
    float4 x = ((const float4*)tin)[idx];
    float4 y;
    y.x = fmaxf((x.x - m0)*s0 + b4v.x, 0.f);
    y.y = fmaxf((x.y - m1)*s1 + b4v.y, 0.f);
    y.z = fmaxf((x.z - m2)*s2 + b4v.z, 0.f);
    y.w = fmaxf((x.w - m3)*s3 + b4v.w, 0.f);
    if (residual) {
        float4 p = ((const float4*)hp)[idx];
        y.x += p.x; y.y += p.y; y.z += p.z; y.w += p.w;
    }
    ((float4*)ho)[idx] = y;
}

// ---------------- fused MHA + mean + residual + LayerNorm + cls GEMM1 + cls stats ----------------
// smem: sWoT 128*128, sW1 128*64, sOm 8*128, sSum 64, sSq 64
__global__ void attn_cls_kernel(const float* __restrict__ qkvN, const float* __restrict__ qkvC,
                                const int* __restrict__ map,
                                const float* __restrict__ hnode,
                                const float* __restrict__ WoT, const float* __restrict__ bo,
                                const float* __restrict__ lng, const float* __restrict__ lnb,
                                const float* __restrict__ W1, const float* __restrict__ b1,
                                float* __restrict__ z, float* __restrict__ stats, int n) {
    extern __shared__ float sm[];
    float* sWoT = sm;                    // 16384
    float* sW1  = sm + 16384;            // 8192
    float* sOm  = sm + 24576;            // 1024
    float* sSum = sm + 25600;            // 64
    float* sSq  = sm + 25664;            // 64
    float4* sW4 = (float4*)sWoT;
    int t = threadIdx.x;
    #pragma unroll
    for (int j = 0; j < 16; j++) sW4[t + j*256] = ((const float4*)WoT)[t + j*256];
    #pragma unroll
    for (int j = 0; j < 8; j++) ((float4*)sW1)[t + j*256] = ((const float4*)W1)[t + j*256];
    if (t < 64) { sSum[t] = 0.f; sSq[t] = 0.f; }
    __syncthreads();

    int lane = t & 31, warp = t >> 5;
    float4 bv  = ((const float4*)bo)[lane];
    float4 gv  = ((const float4*)lng)[lane];
    float4 bbv = ((const float4*)lnb)[lane];
    float b1x = b1[2*lane], b1y = b1[2*lane+1];
    float* so = sOm + warp*128;
    float2 ps = make_float2(0.f,0.f), psq = make_float2(0.f,0.f);

    for (int it = 0; it < 8; it++) {
        int node = blockIdx.x*64 + warp*8 + it;
        if (node >= n) break;
        int cm = map[node];
        cm = cm < 0 ? 0 : (cm > NC-1 ? NC-1 : cm);
        const float4* row0 = (const float4*)(qkvN + (size_t)node*384);
        const float4* row1 = (const float4*)(qkvC + (size_t)cm*384);
        float4 q0 = row0[lane],    q1 = row1[lane];
        float4 k0 = row0[32+lane], k1 = row1[32+lane];
        float4 v0 = row0[64+lane], v1 = row1[64+lane];

        float s00 = q0.x*k0.x + q0.y*k0.y + q0.z*k0.z + q0.w*k0.w;
        float s01 = q0.x*k1.x + q0.y*k1.y + q0.z*k1.z + q0.w*k1.w;
        float s10 = q1.x*k0.x + q1.y*k0.y + q1.z*k0.z + q1.w*k0.w;
        float s11 = q1.x*k1.x + q1.y*k1.y + q1.z*k1.z + q1.w*k1.w;
        #pragma unroll
        for (int m = 1; m <= 2; m <<= 1) {
            s00 += __shfl_xor_sync(0xffffffffu, s00, m);
            s01 += __shfl_xor_sync(0xffffffffu, s01, m);
            s10 += __shfl_xor_sync(0xffffffffu, s10, m);
            s11 += __shfl_xor_sync(0xffffffffu, s11, m);
        }
        s00 *= 0.25f; s01 *= 0.25f; s10 *= 0.25f; s11 *= 0.25f;
        float m0 = fmaxf(s00, s01);
        float e00 = expf(s00-m0), e01 = expf(s01-m0);
        float r0i = 1.f/(e00+e01);
        float p00 = e00*r0i, p01 = e01*r0i;
        float m1 = fmaxf(s10, s11);
        float e10 = expf(s10-m1), e11 = expf(s11-m1);
        float r1i = 1.f/(e10+e11);
        float p10 = e10*r1i, p11 = e11*r1i;

        float4 om;
        om.x = 0.5f*(p00*v0.x + p01*v1.x + p10*v0.x + p11*v1.x);
        om.y = 0.5f*(p00*v0.y + p01*v1.y + p10*v0.y + p11*v1.y);
        om.z = 0.5f*(p00*v0.z + p01*v1.z + p10*v0.z + p11*v1.z);
        om.w = 0.5f*(p00*v0.w + p01*v1.w + p10*v0.w + p11*v1.w);
        ((float4*)so)[lane] = om;
        __syncwarp();

        float4 acc = ((const float4*)(hnode + (size_t)node*128))[lane];
        acc.x += bv.x; acc.y += bv.y; acc.z += bv.z; acc.w += bv.w;
        #pragma unroll 8
        for (int k = 0; k < 128; k++) {
            float ok = so[k];
            float4 wv = sW4[k*32 + lane];
            acc.x = fmaf(ok, wv.x, acc.x);
            acc.y = fmaf(ok, wv.y, acc.y);
            acc.z = fmaf(ok, wv.z, acc.z);
            acc.w = fmaf(ok, wv.w, acc.w);
        }
        float sum = acc.x+acc.y+acc.z+acc.w;
        float sq  = acc.x*acc.x + acc.y*acc.y + acc.z*acc.z + acc.w*acc.w;
        #pragma unroll
        for (int m = 16; m >= 1; m >>= 1) {
            sum += __shfl_xor_sync(0xffffffffu, sum, m);
            sq  += __shfl_xor_sync(0xffffffffu, sq, m);
        }
        float mu = sum * (1.f/128.f);
        float var = sq * (1.f/128.f) - mu*mu;
        float inv = 1.f / sqrtf(var + EPSV);
        float4 o;
        o.x = (acc.x-mu)*inv*gv.x + bbv.x;
        o.y = (acc.y-mu)*inv*gv.y + bbv.y;
        o.z = (acc.z-mu)*inv*gv.z + bbv.z;
        o.w = (acc.w-mu)*inv*gv.w + bbv.w;
        __syncwarp();
        ((float4*)so)[lane] = o;     // reuse so as hfinal row buffer
        __syncwarp();

        // cls GEMM1: z[node][2lane..2lane+1] = hfinal_row @ W1 + b1
        float2 zacc = make_float2(b1x, b1y);
        #pragma unroll 8
        for (int k = 0; k < 128; k++) {
            float a = so[k];
            float2 wv = ((const float2*)sW1)[k*32 + lane];
            zacc.x = fmaf(a, wv.x, zacc.x);
            zacc.y = fmaf(a, wv.y, zacc.y);
        }
        ((float2*)(z + (size_t)node*64))[lane] = zacc;
        ps.x += zacc.x; ps.y += zacc.y;
        psq.x += zacc.x*zacc.x; psq.y += zacc.y*zacc.y;
        __syncwarp();
    }

    atomicAdd(&sSum[2*lane],   ps.x); atomicAdd(&sSum[2*lane+1], ps.y);
    atomicAdd(&sSq [2*lane],   psq.x); atomicAdd(&sSq [2*lane+1], psq.y);
    __syncthreads();
    if (t < 64) { atomicAdd(&stats[t], sSum[t]); atomicAdd(&stats[64+t], sSq[t]); }
}

// ---------------- classifier tail ----------------
__global__ void cls_final_kernel(const float* __restrict__ z, const float* __restrict__ stats,
                                 const float* __restrict__ bng, const float* __restrict__ bnb,
                                 const float* __restrict__ W2, const float* __restrict__ b2,
                                 float* __restrict__ out, int n) {
    __shared__ float sW2[640];
    __shared__ float sb2[16];
    __shared__ float sZ[8][64];
    int t = threadIdx.x, lane = t & 31, warp = t >> 5;
    for (int j = t; j < 640; j += 256) sW2[j] = W2[j];
    if (t < 10) sb2[t] = b2[t];
    __syncthreads();

    float invN = 1.f / (float)n;
    int c0 = 2*lane, c1 = c0 + 1;
    float mu0 = stats[c0]*invN, mu1 = stats[c1]*invN;
    float v0 = stats[64+c0]*invN - mu0*mu0;
    float v1 = stats[64+c1]*invN - mu1*mu1;
    float sc0 = bng[c0] / sqrtf(v0 + EPSV);
    float sc1 = bng[c1] / sqrtf(v1 + EPSV);
    float sh0 = bnb[c0] - mu0*sc0;
    float sh1 = bnb[c1] - mu1*sc1;

    for (int it = 0; it < 8; it++) {
        int row = blockIdx.x*64 + warp*8 + it;
        if (row < n) {
            float2 zv = ((const float2*)(z + (size_t)row*64))[lane];
            sZ[warp][c0] = fmaxf(zv.x*sc0 + sh0, 0.f);
            sZ[warp][c1] = fmaxf(zv.y*sc1 + sh1, 0.f);
            __syncwarp();
            float logit = -1e30f;
            if (lane < 10) {
                logit = sb2[lane];
                #pragma unroll 8
                for (int k = 0; k < 64; k++) logit = fmaf(sZ[warp][k], sW2[k*10+lane], logit);
            }
            float mx = logit;
            #pragma unroll
            for (int m = 16; m >= 1; m >>= 1) mx = fmaxf(mx, __shfl_xor_sync(0xffffffffu, mx, m));
            float ex = (lane < 10) ? expf(logit - mx) : 0.f;
            float s = ex;
            #pragma unroll
            for (int m = 16; m >= 1; m >>= 1) s += __shfl_xor_sync(0xffffffffu, s, m);
            if (lane < 10) out[(size_t)row*10 + lane] = logit - mx - logf(s);
            __syncwarp();
        }
    }
}

// ---------------- host ----------------
extern "C" void kernel_launch(void* const* d_in, const int* in_sizes, int n_in,
                              void* d_out, int out_size) {
    const float* node_features = (const float*)d_in[0];
    const int*   node_ei       = (const int*)d_in[1];
    const float* comm_features = (const float*)d_in[2];
    const int*   comm_ei       = (const int*)d_in[3];
    const int*   n2c           = (const int*)d_in[4];
    const float* node_W   = (const float*)d_in[5];
    const float* node_b   = (const float*)d_in[6];
    const float* node_g   = (const float*)d_in[7];
    const float* node_be  = (const float*)d_in[8];
    const float* comm_W   = (const float*)d_in[9];
    const float* comm_b   = (const float*)d_in[10];
    const float* comm_g   = (const float*)d_in[11];
    const float* comm_be  = (const float*)d_in[12];
    const float* attn_in_w  = (const float*)d_in[13];
    const float* attn_in_b  = (const float*)d_in[14];
    const float* attn_out_w = (const float*)d_in[15];
    const float* attn_out_b = (const float*)d_in[16];
    const float* ln_g  = (const float*)d_in[17];
    const float* ln_b  = (const float*)d_in[18];
    const float* cls_W1 = (const float*)d_in[19];
    const float* cls_b1 = (const float*)d_in[20];
    const float* cls_bg = (const float*)d_in[21];
    const float* cls_bb = (const float*)d_in[22];
    const float* cls_W2 = (const float*)d_in[23];
    const float* cls_b2 = (const float*)d_in[24];
    float* out = (float*)d_out;

    float *bufA, *bufB, *agg, *tmp, *cA, *cB, *cagg, *ctmp, *qkvN, *qkvC, *z1;
    float *stats, *WiT, *WoT;
    cudaGetSymbolAddress((void**)&bufA, g_bufA);
    cudaGetSymbolAddress((void**)&bufB, g_bufB);
    cudaGetSymbolAddress((void**)&agg,  g_agg);
    cudaGetSymbolAddress((void**)&tmp,  g_tmp);
    cudaGetSymbolAddress((void**)&cA,   g_cA);
    cudaGetSymbolAddress((void**)&cB,   g_cB);
    cudaGetSymbolAddress((void**)&cagg, g_cagg);
    cudaGetSymbolAddress((void**)&ctmp, g_ctmp);
    cudaGetSymbolAddress((void**)&qkvN, g_qkvN);
    cudaGetSymbolAddress((void**)&qkvC, g_qkvC);
    cudaGetSymbolAddress((void**)&z1,   g_z1);
    cudaGetSymbolAddress((void**)&stats, g_stats);
    cudaGetSymbolAddress((void**)&WiT,  g_WiT);
    cudaGetSymbolAddress((void**)&WoT,  g_WoT);

    cudaFuncSetAttribute(gemm2_kernel<true>,  cudaFuncAttributeMaxDynamicSharedMemorySize, 98304);
    cudaFuncSetAttribute(gemm2_kernel<false>, cudaFuncAttributeMaxDynamicSharedMemorySize, 98304);
    cudaFuncSetAttribute(attn_cls_kernel,     cudaFuncAttributeMaxDynamicSharedMemorySize, 102912);

    // ---- fused graph prep ----
    zero_kernel<<<(NN+255)/256, 256>>>();
    count_deg2_kernel<<<NBEN + NBEC, 256>>>(node_ei + NE, comm_ei + CE);
    scan_partials2_kernel<<<NBN + NBC, 256>>>();
    scan_top2_kernel<<<2, 64>>>();
    scan_final2_kernel<<<NBN + NBC, 256>>>();
    fill_csr2_kernel<<<NBEN + NBEC, 256>>>(node_ei, node_ei + NE, comm_ei, comm_ei + CE);
    transpose_w_kernel<<<(384*128+255)/256, 256>>>(attn_in_w, attn_out_w);

    // ---- fused GCN stacks ----
    const float* hinN = node_features;
    const float* hinC = comm_features;
    float* houtsN[3] = { bufA, bufB, bufA };
    float* houtsC[3] = { cA, cB, cA };
    int aggWarps = NN + NC;
    for (int i = 0; i < 3; i++) {
        gcn_agg2_kernel<<<(aggWarps*32 + 255)/256, 256>>>(hinN, agg, hinC, cagg);
        gemm2_kernel<true><<<dim3(GN + GC, 1), 256, 98304>>>(
            agg,  node_W + i*16384, node_b + i*128, tmp,  stats + i*256,     NN,
            cagg, comm_W + i*16384, comm_b + i*128, ctmp, stats + (3+i)*256, NC,
            128, 128);
        bn2_kernel<<<((NN+NC)*32 + 255)/256, 256>>>(
            tmp,  stats + i*256,     node_g + i*128, node_be + i*128, hinN, houtsN[i],
            ctmp, stats + (3+i)*256, comm_g + i*128, comm_be + i*128, hinC, houtsC[i],
            i > 0);
        hinN = houtsN[i];
        hinC = houtsC[i];
    }

    // ---- fused qkv GEMM ----
    gemm2_kernel<false><<<dim3(GN + GC, 3), 256, 98304>>>(
        hinN, WiT, attn_in_b, qkvN, nullptr, NN,
        hinC, WiT, attn_in_b, qkvC, nullptr, NC,
        384, 384);

    // ---- fused attention + LayerNorm + cls GEMM1 + stats ----
    attn_cls_kernel<<<(NN+63)/64, 256, 102912>>>(
        qkvN, qkvC, n2c, hinN, WoT, attn_out_b, ln_g, ln_b,
        cls_W1, cls_b1, z1, stats + 6*256, NN);

    // ---- classifier tail ----
    cls_final_kernel<<<(NN+63)/64, 256>>>(z1, stats + 6*256, cls_bg, cls_bb, cls_W2, cls_b2, out, NN);
}